// round 1
// baseline (speedup 1.0000x reference)
#include <cuda_runtime.h>
#include <math.h>

// Problem constants
#define BB 2
#define CC 256
#define HH 64
#define WW 64
#define NN 4096              // HH*WW
#define EPS_IN 1e-5f
#define EPS_NORM 1e-8f
#define SCALE 20.0f

// ---------------- scratch (static device memory; no allocations) ----------
__device__ float g_m[BB * NN];                    // coarse fg mask (0/1)
__device__ float g_bufA[BB * CC * NN];            // ping
__device__ float g_bufB[BB * CC * NN];            // pong
__device__ float g_v[BB * CC * NN];               // V = x * bm
__device__ float g_att[(long)BB * NN * NN];       // scores -> att (in place)
__device__ float g_vis[BB * NN];                  // per-key attention mass
__device__ float g_maxv[1];

// ---------------- reduction helpers ----------------
__device__ __forceinline__ float warpMax(float v) {
#pragma unroll
    for (int o = 16; o; o >>= 1) v = fmaxf(v, __shfl_xor_sync(0xffffffffu, v, o));
    return v;
}
__device__ __forceinline__ float warpSum(float v) {
#pragma unroll
    for (int o = 16; o; o >>= 1) v += __shfl_xor_sync(0xffffffffu, v, o);
    return v;
}

// ---------------- mask: MaxPool2d(8,8) > 0 ----------------
__global__ void k_mask(const float* __restrict__ mask) {
    int gid = blockIdx.x * 256 + threadIdx.x;   // < 8192
    int b = gid >> 12;
    int j = gid & 4095;
    int py = j >> 6, px = j & 63;
    const float* mp = mask + (long)b * 262144 + (py * 8) * 512 + px * 8;
    float mx = 0.f;
#pragma unroll
    for (int dy = 0; dy < 8; dy++)
#pragma unroll
        for (int dx = 0; dx < 8; dx++) mx = fmaxf(mx, mp[dy * 512 + dx]);
    g_m[gid] = (mx > 0.f) ? 1.f : 0.f;
}

// ---------------- conv3x3 SAME, 256->256, tiled ----------------
// grid: (16 spatial tiles, 8 co tiles, B); block 256
__global__ __launch_bounds__(256) void k_conv3(const float* __restrict__ in,
                                               const float* __restrict__ w,
                                               float* __restrict__ out) {
    __shared__ float sIn[8][18][19];
    __shared__ float sW[32][72];   // [co][ci*9+k]
    int tid = threadIdx.x;
    int b = blockIdx.z;
    int co0 = blockIdx.y << 5;
    int ty = (blockIdx.x >> 2) << 4;
    int tx = (blockIdx.x & 3) << 4;
    int lane = tid & 63;
    int cg = tid >> 6;   // 0..3
    int py_[4], px_[4];
#pragma unroll
    for (int p = 0; p < 4; p++) {
        int pidx = lane + (p << 6);
        py_[p] = pidx >> 4;
        px_[p] = pidx & 15;
    }
    float acc[8][4];
#pragma unroll
    for (int j = 0; j < 8; j++)
#pragma unroll
        for (int p = 0; p < 4; p++) acc[j][p] = 0.f;

    const float* inb = in + (long)b * CC * NN;
    for (int ci0 = 0; ci0 < CC; ci0 += 8) {
        for (int idx = tid; idx < 8 * 18 * 18; idx += 256) {
            int ci = idx / 324;
            int r = idx - ci * 324;
            int iy = r / 18;
            int ix = r - iy * 18;
            int gy = ty + iy - 1, gx = tx + ix - 1;
            float v = 0.f;
            if ((unsigned)gy < 64u && (unsigned)gx < 64u)
                v = inb[((ci0 + ci) << 12) + (gy << 6) + gx];
            sIn[ci][iy][ix] = v;
        }
        for (int idx = tid; idx < 2304; idx += 256) {
            int co = idx / 72;
            int r = idx - co * 72;
            sW[co][r] = w[(co0 + co) * 2304 + ci0 * 9 + r];
        }
        __syncthreads();
#pragma unroll 1
        for (int ci = 0; ci < 8; ci++) {
#pragma unroll
            for (int k = 0; k < 9; k++) {
                int ky = k / 3, kx = k - ky * 3;
                float wv[8];
#pragma unroll
                for (int j = 0; j < 8; j++) wv[j] = sW[cg + (j << 2)][ci * 9 + k];
#pragma unroll
                for (int p = 0; p < 4; p++) {
                    float iv = sIn[ci][py_[p] + ky][px_[p] + kx];
#pragma unroll
                    for (int j = 0; j < 8; j++) acc[j][p] = fmaf(wv[j], iv, acc[j][p]);
                }
            }
        }
        __syncthreads();
    }
    float* ob = out + (long)b * CC * NN;
#pragma unroll
    for (int j = 0; j < 8; j++) {
        int co = co0 + cg + (j << 2);
#pragma unroll
        for (int p = 0; p < 4; p++)
            ob[(co << 12) + ((ty + py_[p]) << 6) + tx + px_[p]] = acc[j][p];
    }
}

// ---------------- instance norm (+optional residual add) + relu ----------
// grid: B*C blocks; block 256
__global__ __launch_bounds__(256) void k_inorm(const float* __restrict__ t,
                                               const float* __restrict__ xadd,
                                               float* __restrict__ o, int add) {
    long base = (long)blockIdx.x * NN;
    int tid = threadIdx.x;
    float s = 0.f, s2 = 0.f;
    for (int i = tid; i < NN; i += 256) {
        float v = t[base + i];
        s += v;
        s2 = fmaf(v, v, s2);
    }
    __shared__ float sh[16];
    __shared__ float smu, srs;
    s = warpSum(s);
    s2 = warpSum(s2);
    int wi = tid >> 5, l = tid & 31;
    if (l == 0) { sh[wi] = s; sh[8 + wi] = s2; }
    __syncthreads();
    if (tid == 0) {
        float a = 0.f, b2 = 0.f;
#pragma unroll
        for (int i = 0; i < 8; i++) { a += sh[i]; b2 += sh[8 + i]; }
        float mu = a * (1.f / NN);
        float var = b2 * (1.f / NN) - mu * mu;
        smu = mu;
        srs = rsqrtf(var + EPS_IN);
    }
    __syncthreads();
    float mu = smu, rs = srs;
    if (add) {
        for (int i = tid; i < NN; i += 256) {
            float v = (t[base + i] - mu) * rs + xadd[base + i];
            o[base + i] = fmaxf(v, 0.f);
        }
    } else {
        for (int i = tid; i < NN; i += 256) {
            float v = (t[base + i] - mu) * rs;
            o[base + i] = fmaxf(v, 0.f);
        }
    }
}

// ---------------- per-pixel channel L2-normalize + build V ----------------
__global__ void k_nfv(const float* __restrict__ feat, const float* __restrict__ x,
                      float* __restrict__ nf, float* __restrict__ v) {
    int gid = blockIdx.x * 256 + threadIdx.x;   // < 8192
    int b = gid >> 12;
    int px = gid & 4095;
    const float* fb = feat + (long)b * CC * NN + px;
    float s = 0.f;
    for (int c = 0; c < CC; c++) {
        float f = fb[c << 12];
        s = fmaf(f, f, s);
    }
    float rn = 1.f / (sqrtf(s) + EPS_NORM);
    float bm = (g_m[gid] > 0.5f) ? 0.f : 1.f;
    const float* xb = x + (long)b * CC * NN + px;
    float* nfb = nf + (long)b * CC * NN + px;
    float* vb = v + (long)b * CC * NN + px;
    for (int c = 0; c < CC; c++) {
        nfb[c << 12] = fb[c << 12] * rn;
        vb[c << 12] = xb[c << 12] * bm;
    }
}

// ---------------- GEMM: score[q][k] = 20 * sum_c nf[c][q]*nf[c][k] ----------
// grid: (32 k-tiles, 32 q-tiles, B); block 256; 128x128x16
__global__ __launch_bounds__(256) void k_gemm_score(const float* __restrict__ nf,
                                                    float* __restrict__ att) {
    __shared__ float As[16][128];
    __shared__ float Bs[16][128];
    int b = blockIdx.z;
    const float* A = nf + (long)b * CC * NN;
    int q0 = blockIdx.y << 7;
    int k0 = blockIdx.x << 7;
    float* Cb = att + (long)b * NN * NN;
    int tid = threadIdx.x;
    int mb = (tid >> 4) << 3;
    int nb = (tid & 15) << 3;
    float acc[8][8];
#pragma unroll
    for (int i = 0; i < 8; i++)
#pragma unroll
        for (int j = 0; j < 8; j++) acc[i][j] = 0.f;

    for (int c0 = 0; c0 < CC; c0 += 16) {
#pragma unroll
        for (int t = 0; t < 2; t++) {
            int idx = tid + (t << 8);
            int row = idx >> 5;
            int col = (idx & 31) << 2;
            *(float4*)&As[row][col] = *(const float4*)(A + (long)(c0 + row) * NN + q0 + col);
            *(float4*)&Bs[row][col] = *(const float4*)(A + (long)(c0 + row) * NN + k0 + col);
        }
        __syncthreads();
#pragma unroll
        for (int kk = 0; kk < 16; kk++) {
            float a[8], bb[8];
            *(float4*)&a[0] = *(float4*)&As[kk][mb];
            *(float4*)&a[4] = *(float4*)&As[kk][mb + 4];
            *(float4*)&bb[0] = *(float4*)&Bs[kk][nb];
            *(float4*)&bb[4] = *(float4*)&Bs[kk][nb + 4];
#pragma unroll
            for (int i = 0; i < 8; i++)
#pragma unroll
                for (int j = 0; j < 8; j++) acc[i][j] = fmaf(a[i], bb[j], acc[i][j]);
        }
        __syncthreads();
    }
#pragma unroll
    for (int i = 0; i < 8; i++) {
        long ro = (long)(q0 + mb + i) * NN + k0 + nb;
        float4 o0, o1;
        o0.x = acc[i][0] * SCALE; o0.y = acc[i][1] * SCALE;
        o0.z = acc[i][2] * SCALE; o0.w = acc[i][3] * SCALE;
        o1.x = acc[i][4] * SCALE; o1.y = acc[i][5] * SCALE;
        o1.z = acc[i][6] * SCALE; o1.w = acc[i][7] * SCALE;
        *(float4*)(Cb + ro) = o0;
        *(float4*)(Cb + ro + 4) = o1;
    }
}

// ---------------- masked softmax over keys, in place --------------------
// grid: (4096, B); block 256
__global__ __launch_bounds__(256) void k_softmax(float* __restrict__ att) {
    int b = blockIdx.y;
    int q = blockIdx.x;
    float* row = att + (long)b * NN * NN + (long)q * NN;
    int tid = threadIdx.x;
    const float* mrow = g_m + (b << 12);
    if (mrow[q] <= 0.5f) {           // invalid query row -> zeros
        float4 z = make_float4(0.f, 0.f, 0.f, 0.f);
        for (int i = tid; i < NN / 4; i += 256) ((float4*)row)[i] = z;
        return;
    }
    float vals[16];
    float mx = -1e30f;
#pragma unroll
    for (int t = 0; t < 16; t++) {
        int k = tid + (t << 8);
        float s = row[k];
        s = (mrow[k] <= 0.5f) ? s : -1e30f;   // key valid iff bg (m==0)
        vals[t] = s;
        mx = fmaxf(mx, s);
    }
    __shared__ float sh[8];
    __shared__ float bval;
    mx = warpMax(mx);
    int wi = tid >> 5, l = tid & 31;
    if (l == 0) sh[wi] = mx;
    __syncthreads();
    if (tid == 0) {
        float m2 = sh[0];
#pragma unroll
        for (int i = 1; i < 8; i++) m2 = fmaxf(m2, sh[i]);
        bval = m2;
    }
    __syncthreads();
    mx = bval;
    float sum = 0.f;
#pragma unroll
    for (int t = 0; t < 16; t++) {
        float e = __expf(vals[t] - mx);
        vals[t] = e;
        sum += e;
    }
    sum = warpSum(sum);
    __syncthreads();
    if (l == 0) sh[wi] = sum;
    __syncthreads();
    if (tid == 0) {
        float s2 = 0.f;
#pragma unroll
        for (int i = 0; i < 8; i++) s2 += sh[i];
        bval = 1.f / s2;
    }
    __syncthreads();
    float rinv = bval;
#pragma unroll
    for (int t = 0; t < 16; t++) row[tid + (t << 8)] = vals[t] * rinv;
}

// ---------------- visatt[k] = sum_q att[q][k] ----------------------------
// grid: (64, B); block 256 (4 q-lanes x 64 k)
__global__ void k_visatt(const float* __restrict__ att) {
    int b = blockIdx.y;
    int k0 = blockIdx.x << 6;
    int kk = threadIdx.x & 63;
    int qq = threadIdx.x >> 6;
    const float* base = att + (long)b * NN * NN + k0 + kk;
    float s = 0.f;
    for (int q = qq; q < NN; q += 4) s += base[(long)q << 12];
    __shared__ float sh[256];
    sh[threadIdx.x] = s;
    __syncthreads();
    if (threadIdx.x < 64) {
        float tot = sh[threadIdx.x] + sh[threadIdx.x + 64] +
                    sh[threadIdx.x + 128] + sh[threadIdx.x + 192];
        g_vis[(b << 12) + k0 + threadIdx.x] = tot;
    }
}

// ---------------- GEMM: att_fore[c][q] = sum_k V[c][k]*att[q][k] ---------
// grid: (32 q-tiles, 2 c-tiles, B); block 256; 128x128x16, transposed loads
__global__ __launch_bounds__(256) void k_gemm_av(const float* __restrict__ V,
                                                 const float* __restrict__ att,
                                                 float* __restrict__ out) {
    __shared__ float As[16][128];
    __shared__ float Bs[16][128];
    int b = blockIdx.z;
    const float* Ab = V + (long)b * CC * NN;
    const float* Bb = att + (long)b * NN * NN;
    int m0 = blockIdx.y << 7;
    int n0 = blockIdx.x << 7;
    int tid = threadIdx.x;
    int mb = (tid >> 4) << 3;
    int nb = (tid & 15) << 3;
    float acc[8][8];
#pragma unroll
    for (int i = 0; i < 8; i++)
#pragma unroll
        for (int j = 0; j < 8; j++) acc[i][j] = 0.f;

    for (int kc = 0; kc < NN; kc += 16) {
#pragma unroll
        for (int t = 0; t < 2; t++) {
            int fid = tid + (t << 8);
            int rr = fid >> 2;
            int kb = (fid & 3) << 2;
            float4 av = *(const float4*)(Ab + (long)(m0 + rr) * NN + kc + kb);
            As[kb + 0][rr] = av.x; As[kb + 1][rr] = av.y;
            As[kb + 2][rr] = av.z; As[kb + 3][rr] = av.w;
            float4 bv = *(const float4*)(Bb + (long)(n0 + rr) * NN + kc + kb);
            Bs[kb + 0][rr] = bv.x; Bs[kb + 1][rr] = bv.y;
            Bs[kb + 2][rr] = bv.z; Bs[kb + 3][rr] = bv.w;
        }
        __syncthreads();
#pragma unroll
        for (int kk = 0; kk < 16; kk++) {
            float a[8], bb[8];
            *(float4*)&a[0] = *(float4*)&As[kk][mb];
            *(float4*)&a[4] = *(float4*)&As[kk][mb + 4];
            *(float4*)&bb[0] = *(float4*)&Bs[kk][nb];
            *(float4*)&bb[4] = *(float4*)&Bs[kk][nb + 4];
#pragma unroll
            for (int i = 0; i < 8; i++)
#pragma unroll
                for (int j = 0; j < 8; j++) acc[i][j] = fmaf(a[i], bb[j], acc[i][j]);
        }
        __syncthreads();
    }
    float* ob = out + (long)b * CC * NN;
#pragma unroll
    for (int i = 0; i < 8; i++) {
        long ro = (long)(m0 + mb + i) * NN + n0 + nb;
        *(float4*)(ob + ro) = *(float4*)&acc[i][0];
        *(float4*)(ob + ro + 4) = *(float4*)&acc[i][4];
    }
}

// ---------------- fuse 1x1 conv over concat(att_fore, x) + compose -------
// grid: (32 px-tiles, 2 co-tiles, B); block 256
__global__ __launch_bounds__(256) void k_gemm_fuse(const float* __restrict__ wf,
                                                   const float* __restrict__ afore,
                                                   const float* __restrict__ x,
                                                   float* __restrict__ out) {
    __shared__ float As[16][128];
    __shared__ float Bs[16][128];
    int b = blockIdx.z;
    int m0 = blockIdx.y << 7;   // co
    int n0 = blockIdx.x << 7;   // px
    int tid = threadIdx.x;
    int mb = (tid >> 4) << 3;
    int nb = (tid & 15) << 3;
    float acc[8][8];
#pragma unroll
    for (int i = 0; i < 8; i++)
#pragma unroll
        for (int j = 0; j < 8; j++) acc[i][j] = 0.f;

    for (int kc = 0; kc < 2 * CC; kc += 16) {
#pragma unroll
        for (int t = 0; t < 2; t++) {
            int fid = tid + (t << 8);
            int rr = fid >> 2;
            int kb = (fid & 3) << 2;
            float4 av = *(const float4*)(wf + (long)(m0 + rr) * 512 + kc + kb);
            As[kb + 0][rr] = av.x; As[kb + 1][rr] = av.y;
            As[kb + 2][rr] = av.z; As[kb + 3][rr] = av.w;
            int idx = fid;
            int row = idx >> 5;
            int col = (idx & 31) << 2;
            int kki = kc + row;
            const float* src = (kki < CC) ? (afore + (long)(b * CC + kki) * NN)
                                          : (x + (long)(b * CC + kki - CC) * NN);
            *(float4*)&Bs[row][col] = *(const float4*)(src + n0 + col);
        }
        __syncthreads();
#pragma unroll
        for (int kk = 0; kk < 16; kk++) {
            float a[8], bb[8];
            *(float4*)&a[0] = *(float4*)&As[kk][mb];
            *(float4*)&a[4] = *(float4*)&As[kk][mb + 4];
            *(float4*)&bb[0] = *(float4*)&Bs[kk][nb];
            *(float4*)&bb[4] = *(float4*)&Bs[kk][nb + 4];
#pragma unroll
            for (int i = 0; i < 8; i++)
#pragma unroll
                for (int j = 0; j < 8; j++) acc[i][j] = fmaf(a[i], bb[j], acc[i][j]);
        }
        __syncthreads();
    }
    const float* xb = x + (long)b * CC * NN;
    const float* mrow = g_m + (b << 12);
#pragma unroll
    for (int i = 0; i < 8; i++) {
        int co = m0 + mb + i;
#pragma unroll
        for (int j = 0; j < 8; j++) {
            int px = n0 + nb + j;
            float msk = mrow[px];
            float val = (msk > 0.5f) ? acc[i][j] : xb[(co << 12) + px];
            out[((b * CC + co) << 12) + px] = val;
        }
    }
}

// ---------------- global max of visatt ----------------------------------
__global__ void k_vismax() {
    float mx = -1e30f;
    for (int i = threadIdx.x; i < BB * NN; i += 256) mx = fmaxf(mx, g_vis[i]);
    mx = warpMax(mx);
    __shared__ float sh[8];
    if ((threadIdx.x & 31) == 0) sh[threadIdx.x >> 5] = mx;
    __syncthreads();
    if (threadIdx.x == 0) {
        float m2 = sh[0];
#pragma unroll
        for (int i = 1; i < 8; i++) m2 = fmaxf(m2, sh[i]);
        g_maxv[0] = m2;
    }
}

// ---------------- attmask: 8x nearest upsample / max --------------------
__global__ void k_attmask(float* __restrict__ o) {
    int i = blockIdx.x * 256 + threadIdx.x;   // < 524288
    int b = i >> 18;
    int r = i & 262143;
    int Y = r >> 9, X = r & 511;
    o[i] = g_vis[(b << 12) + ((Y >> 3) << 6) + (X >> 3)] / g_maxv[0];
}

// ---------------- launch -------------------------------------------------
extern "C" void kernel_launch(void* const* d_in, const int* in_sizes, int n_in,
                              void* d_out, int out_size) {
    const float* x = nullptr;
    const float* mask = nullptr;
    const float* w1 = nullptr;
    const float* w2 = nullptr;
    const float* wf = nullptr;
    int seen589 = 0;
    for (int i = 0; i < n_in; i++) {
        switch (in_sizes[i]) {
            case 2097152: x = (const float*)d_in[i]; break;
            case 524288:  mask = (const float*)d_in[i]; break;
            case 589824:
                if (seen589++ == 0) w1 = (const float*)d_in[i];
                else w2 = (const float*)d_in[i];
                break;
            case 131072:  wf = (const float*)d_in[i]; break;
            default: break;
        }
    }

    float *bufA, *bufB, *vv, *att;
    cudaGetSymbolAddress((void**)&bufA, g_bufA);
    cudaGetSymbolAddress((void**)&bufB, g_bufB);
    cudaGetSymbolAddress((void**)&vv, g_v);
    cudaGetSymbolAddress((void**)&att, g_att);

    float* out = (float*)d_out;
    float* attm = out + (long)BB * CC * NN;

    k_mask<<<32, 256>>>(mask);
    k_conv3<<<dim3(16, 8, BB), 256>>>(x, w1, bufA);
    k_inorm<<<BB * CC, 256>>>(bufA, nullptr, bufB, 0);
    k_conv3<<<dim3(16, 8, BB), 256>>>(bufB, w2, bufA);
    k_inorm<<<BB * CC, 256>>>(bufA, x, bufB, 1);          // bufB = feat
    k_nfv<<<32, 256>>>(bufB, x, bufA, vv);                // bufA = nfeat
    k_gemm_score<<<dim3(32, 32, BB), 256>>>(bufA, att);
    k_softmax<<<dim3(4096, BB), 256>>>(att);
    k_visatt<<<dim3(64, BB), 256>>>(att);
    k_gemm_av<<<dim3(32, 2, BB), 256>>>(vv, att, bufB);   // bufB = att_fore
    k_vismax<<<1, 256>>>();
    k_gemm_fuse<<<dim3(32, 2, BB), 256>>>(wf, bufB, x, out);
    k_attmask<<<2048, 256>>>(attm);
}

// round 2
// speedup vs baseline: 1.6547x; 1.6547x over previous
#include <cuda_runtime.h>
#include <math.h>

#define BB 2
#define CC 256
#define HH 64
#define WW 64
#define NN 4096
#define EPS_IN 1e-5f
#define EPS_NORM 1e-8f
#define SCALE 20.0f
#define PAD128(v) (((v) + 127) & ~127)

// ---------------- static scratch ----------------
__device__ float g_m[BB * NN];
__device__ int   g_qidx[BB * NN];
__device__ int   g_kidx[BB * NN];
__device__ int   g_nq[BB];
__device__ int   g_nk[BB];
__device__ float g_bufA[BB * CC * NN];   // conv ping / AFq (att_fore compacted)
__device__ float g_bufB[BB * CC * NN];   // feat
__device__ float g_rn[BB * NN];
__device__ float g_Qc[BB * CC * NN];
__device__ float g_Kc[BB * CC * NN];
__device__ float g_Vc[BB * CC * NN];
__device__ float g_Xq[BB * CC * NN];
__device__ float g_att[(long)BB * NN * NN];
__device__ float g_vis[BB * NN];
__device__ float g_maxv[1];

__device__ __forceinline__ float warpMax(float v) {
#pragma unroll
    for (int o = 16; o; o >>= 1) v = fmaxf(v, __shfl_xor_sync(0xffffffffu, v, o));
    return v;
}
__device__ __forceinline__ float warpSum(float v) {
#pragma unroll
    for (int o = 16; o; o >>= 1) v += __shfl_xor_sync(0xffffffffu, v, o);
    return v;
}

// ---------------- mask: MaxPool2d(8,8) > 0; also zero g_vis ---------------
__global__ void k_mask(const float* __restrict__ mask) {
    int gid = blockIdx.x * 256 + threadIdx.x;   // < 8192
    int b = gid >> 12;
    int j = gid & 4095;
    int py = j >> 6, px = j & 63;
    const float* mp = mask + (long)b * 262144 + (py * 8) * 512 + px * 8;
    float mx = 0.f;
#pragma unroll
    for (int dy = 0; dy < 8; dy++)
#pragma unroll
        for (int dx = 0; dx < 8; dx++) mx = fmaxf(mx, mp[dy * 512 + dx]);
    g_m[gid] = (mx > 0.f) ? 1.f : 0.f;
    g_vis[gid] = 0.f;
}

// ---------------- deterministic compaction (1 block / batch) --------------
__global__ __launch_bounds__(256) void k_compact() {
    int b = blockIdx.x;
    int tid = threadIdx.x;
    __shared__ int wsum[8];
    __shared__ int baseq, basek;
    if (tid == 0) { baseq = 0; basek = 0; }
    __syncthreads();
    for (int chunk = 0; chunk < 16; chunk++) {
        int px = (chunk << 8) + tid;
        int vq = (g_m[(b << 12) + px] > 0.5f) ? 1 : 0;
        unsigned bal = __ballot_sync(0xffffffffu, vq);
        int lane = tid & 31, w = tid >> 5;
        int pre = __popc(bal & ((1u << lane) - 1u));
        if (lane == 0) wsum[w] = __popc(bal);
        __syncthreads();
        int woff = 0, tot = 0;
#pragma unroll
        for (int i = 0; i < 8; i++) {
            if (i < w) woff += wsum[i];
            tot += wsum[i];
        }
        int bq = baseq, bk = basek;
        int qbefore = woff + pre;
        if (vq) g_qidx[(b << 12) + bq + qbefore] = px;
        else    g_kidx[(b << 12) + bk + (tid - qbefore)] = px;
        __syncthreads();
        if (tid == 0) { baseq = bq + tot; basek = bk + (256 - tot); }
        __syncthreads();
    }
    if (tid == 0) { g_nq[b] = baseq; g_nk[b] = basek; }
}

// ---------------- conv3x3 SAME, 256->256, tiled ----------------
__global__ __launch_bounds__(256) void k_conv3(const float* __restrict__ in,
                                               const float* __restrict__ w,
                                               float* __restrict__ out) {
    __shared__ float sIn[8][18][19];
    __shared__ float sWt[72][36];   // [ci*9+k][co], padded
    int tid = threadIdx.x;
    int b = blockIdx.z;
    int co0 = blockIdx.y << 5;
    int ty = (blockIdx.x >> 2) << 4;
    int tx = (blockIdx.x & 3) << 4;
    int lane = tid & 63;
    int cg = tid >> 6;   // 0..3  -> co group cg*8..cg*8+7
    int py_[4], px_[4];
#pragma unroll
    for (int p = 0; p < 4; p++) {
        int pidx = lane + (p << 6);
        py_[p] = pidx >> 4;
        px_[p] = pidx & 15;
    }
    float acc[8][4];
#pragma unroll
    for (int j = 0; j < 8; j++)
#pragma unroll
        for (int p = 0; p < 4; p++) acc[j][p] = 0.f;

    const float* inb = in + (long)b * CC * NN;
    for (int ci0 = 0; ci0 < CC; ci0 += 8) {
        for (int idx = tid; idx < 8 * 18 * 18; idx += 256) {
            int ci = idx / 324;
            int r = idx - ci * 324;
            int iy = r / 18;
            int ix = r - iy * 18;
            int gy = ty + iy - 1, gx = tx + ix - 1;
            float v = 0.f;
            if ((unsigned)gy < 64u && (unsigned)gx < 64u)
                v = inb[((ci0 + ci) << 12) + (gy << 6) + gx];
            sIn[ci][iy][ix] = v;
        }
        for (int idx = tid; idx < 2304; idx += 256) {
            int co = idx / 72;
            int r = idx - co * 72;
            sWt[r][co] = w[(co0 + co) * 2304 + ci0 * 9 + r];
        }
        __syncthreads();
#pragma unroll 1
        for (int ci = 0; ci < 8; ci++) {
#pragma unroll
            for (int k = 0; k < 9; k++) {
                int ky = k / 3, kx = k - ky * 3;
                float wv[8];
                *(float4*)&wv[0] = *(float4*)&sWt[ci * 9 + k][cg << 3];
                *(float4*)&wv[4] = *(float4*)&sWt[ci * 9 + k][(cg << 3) + 4];
#pragma unroll
                for (int p = 0; p < 4; p++) {
                    float iv = sIn[ci][py_[p] + ky][px_[p] + kx];
#pragma unroll
                    for (int j = 0; j < 8; j++) acc[j][p] = fmaf(wv[j], iv, acc[j][p]);
                }
            }
        }
        __syncthreads();
    }
    float* ob = out + (long)b * CC * NN;
#pragma unroll
    for (int j = 0; j < 8; j++) {
        int co = co0 + (cg << 3) + j;
#pragma unroll
        for (int p = 0; p < 4; p++)
            ob[(co << 12) + ((ty + py_[p]) << 6) + tx + px_[p]] = acc[j][p];
    }
}

// ---------------- instance norm (+optional residual) + relu ---------------
__global__ __launch_bounds__(256) void k_inorm(const float* __restrict__ t,
                                               const float* __restrict__ xadd,
                                               float* __restrict__ o, int add) {
    long base = (long)blockIdx.x * NN;
    int tid = threadIdx.x;
    float s = 0.f, s2 = 0.f;
    for (int i = tid; i < NN; i += 256) {
        float v = t[base + i];
        s += v;
        s2 = fmaf(v, v, s2);
    }
    __shared__ float sh[16];
    __shared__ float smu, srs;
    s = warpSum(s);
    s2 = warpSum(s2);
    int wi = tid >> 5, l = tid & 31;
    if (l == 0) { sh[wi] = s; sh[8 + wi] = s2; }
    __syncthreads();
    if (tid == 0) {
        float a = 0.f, b2 = 0.f;
#pragma unroll
        for (int i = 0; i < 8; i++) { a += sh[i]; b2 += sh[8 + i]; }
        float mu = a * (1.f / NN);
        float var = b2 * (1.f / NN) - mu * mu;
        smu = mu;
        srs = rsqrtf(var + EPS_IN);
    }
    __syncthreads();
    float mu = smu, rs = srs;
    if (add) {
        for (int i = tid; i < NN; i += 256)
            o[base + i] = fmaxf((t[base + i] - mu) * rs + xadd[base + i], 0.f);
    } else {
        for (int i = tid; i < NN; i += 256)
            o[base + i] = fmaxf((t[base + i] - mu) * rs, 0.f);
    }
}

// ---------------- per-pixel channel L2 norm reciprocal --------------------
__global__ void k_rn(const float* __restrict__ feat) {
    int gid = blockIdx.x * 256 + threadIdx.x;   // < 8192
    int b = gid >> 12;
    int px = gid & 4095;
    const float* fb = feat + (long)b * CC * NN + px;
    float s = 0.f;
    for (int c = 0; c < CC; c++) {
        float f = fb[c << 12];
        s = fmaf(f, f, s);
    }
    g_rn[gid] = 1.f / (sqrtf(s) + EPS_NORM);
}

// ---------------- gather compacted matrices -------------------------------
// grid (16, 2, BB); block 256. y=0: queries -> Qc,Xq ; y=1: keys -> Kc,Vc
__global__ __launch_bounds__(256) void k_gather(const float* __restrict__ feat,
                                                const float* __restrict__ x) {
    int b = blockIdx.z;
    int side = blockIdx.y;
    int i = (blockIdx.x << 8) + threadIdx.x;
    int n = side ? g_nk[b] : g_nq[b];
    int npad = PAD128(n);
    if (i >= npad) return;
    float* A = side ? g_Kc : g_Qc;
    float* B2 = side ? g_Vc : g_Xq;
    long off = (long)b * CC * NN;
    if (i < n) {
        int px = side ? g_kidx[(b << 12) + i] : g_qidx[(b << 12) + i];
        float rn = g_rn[(b << 12) + px];
        const float* fb = feat + off + px;
        const float* xb = x + off + px;
        for (int c = 0; c < CC; c++) {
            A[off + (c << 12) + i] = fb[c << 12] * rn;
            B2[off + (c << 12) + i] = xb[c << 12];
        }
    } else {
        for (int c = 0; c < CC; c++) {
            A[off + (c << 12) + i] = 0.f;
            B2[off + (c << 12) + i] = 0.f;
        }
    }
}

// ---------------- score GEMM (compacted): 128x128x16 ----------------------
__global__ __launch_bounds__(256) void k_gemm_score(const float* __restrict__ Q,
                                                    const float* __restrict__ K,
                                                    float* __restrict__ att) {
    int b = blockIdx.z;
    int q0 = blockIdx.y << 7;
    int k0 = blockIdx.x << 7;
    if (q0 >= PAD128(g_nq[b]) || k0 >= PAD128(g_nk[b])) return;
    __shared__ float As[16][128];
    __shared__ float Bs[16][128];
    const float* Ab = Q + (long)b * CC * NN;
    const float* Bb = K + (long)b * CC * NN;
    float* Cb = att + (long)b * NN * NN;
    int tid = threadIdx.x;
    int mb = (tid >> 4) << 3;
    int nb = (tid & 15) << 3;
    float acc[8][8];
#pragma unroll
    for (int i = 0; i < 8; i++)
#pragma unroll
        for (int j = 0; j < 8; j++) acc[i][j] = 0.f;

    for (int c0 = 0; c0 < CC; c0 += 16) {
#pragma unroll
        for (int t = 0; t < 2; t++) {
            int idx = tid + (t << 8);
            int row = idx >> 5;
            int col = (idx & 31) << 2;
            *(float4*)&As[row][col] = *(const float4*)(Ab + (long)(c0 + row) * NN + q0 + col);
            *(float4*)&Bs[row][col] = *(const float4*)(Bb + (long)(c0 + row) * NN + k0 + col);
        }
        __syncthreads();
#pragma unroll
        for (int kk = 0; kk < 16; kk++) {
            float a[8], bb[8];
            *(float4*)&a[0] = *(float4*)&As[kk][mb];
            *(float4*)&a[4] = *(float4*)&As[kk][mb + 4];
            *(float4*)&bb[0] = *(float4*)&Bs[kk][nb];
            *(float4*)&bb[4] = *(float4*)&Bs[kk][nb + 4];
#pragma unroll
            for (int i = 0; i < 8; i++)
#pragma unroll
                for (int j = 0; j < 8; j++) acc[i][j] = fmaf(a[i], bb[j], acc[i][j]);
        }
        __syncthreads();
    }
#pragma unroll
    for (int i = 0; i < 8; i++) {
        long ro = (long)(q0 + mb + i) * NN + k0 + nb;
        float4 o0, o1;
        o0.x = acc[i][0] * SCALE; o0.y = acc[i][1] * SCALE;
        o0.z = acc[i][2] * SCALE; o0.w = acc[i][3] * SCALE;
        o1.x = acc[i][4] * SCALE; o1.y = acc[i][5] * SCALE;
        o1.z = acc[i][6] * SCALE; o1.w = acc[i][7] * SCALE;
        *(float4*)(Cb + ro) = o0;
        *(float4*)(Cb + ro + 4) = o1;
    }
}

// ---------------- softmax over compacted keys ------------------------------
__global__ __launch_bounds__(256) void k_softmax(float* __restrict__ att) {
    int b = blockIdx.y;
    int i = blockIdx.x;
    int nq = g_nq[b];
    if (i >= nq) return;
    int nk = g_nk[b];
    int nkp = PAD128(nk);
    float* row = att + (long)b * NN * NN + (long)i * NN;
    int tid = threadIdx.x;
    float vals[16];
    float mx = -1e30f;
    int nt = (nkp + 255) >> 8;
#pragma unroll
    for (int t = 0; t < 16; t++) {
        if (t >= nt) break;
        int k = tid + (t << 8);
        float s = (k < nk) ? row[k] : -1e30f;
        vals[t] = s;
        mx = fmaxf(mx, s);
    }
    __shared__ float sh[8];
    __shared__ float bval;
    mx = warpMax(mx);
    int wi = tid >> 5, l = tid & 31;
    if (l == 0) sh[wi] = mx;
    __syncthreads();
    if (tid == 0) {
        float m2 = sh[0];
#pragma unroll
        for (int ii = 1; ii < 8; ii++) m2 = fmaxf(m2, sh[ii]);
        bval = m2;
    }
    __syncthreads();
    mx = bval;
    float sum = 0.f;
#pragma unroll
    for (int t = 0; t < 16; t++) {
        if (t >= nt) break;
        float e = __expf(vals[t] - mx);
        vals[t] = e;
        sum += e;
    }
    sum = warpSum(sum);
    __syncthreads();
    if (l == 0) sh[wi] = sum;
    __syncthreads();
    if (tid == 0) {
        float s2 = 0.f;
#pragma unroll
        for (int ii = 0; ii < 8; ii++) s2 += sh[ii];
        bval = 1.f / s2;
    }
    __syncthreads();
    float rinv = bval;
#pragma unroll
    for (int t = 0; t < 16; t++) {
        if (t >= nt) break;
        int k = tid + (t << 8);
        row[k] = (k < nk) ? vals[t] * rinv : 0.f;
    }
}

// ---------------- visatt: column sums of compacted att, scattered ---------
__global__ void k_visatt(const float* __restrict__ att) {
    int b = blockIdx.y;
    int k0 = blockIdx.x << 6;
    int nk = g_nk[b];
    if (k0 >= nk) return;
    int nq = g_nq[b];
    int kk = threadIdx.x & 63;
    int qq = threadIdx.x >> 6;
    const float* base = att + (long)b * NN * NN + k0 + kk;
    float s = 0.f;
    for (int q = qq; q < nq; q += 4) s += base[(long)q << 12];
    __shared__ float sh[256];
    sh[threadIdx.x] = s;
    __syncthreads();
    if (threadIdx.x < 64) {
        int k = k0 + threadIdx.x;
        if (k < nk) {
            float tot = sh[threadIdx.x] + sh[threadIdx.x + 64] +
                        sh[threadIdx.x + 128] + sh[threadIdx.x + 192];
            g_vis[(b << 12) + g_kidx[(b << 12) + k]] = tot;
        }
    }
}

// ---------------- AV GEMM: AFq[c][i] = sum_j Vc[c][j] * P[i][j] ------------
__global__ __launch_bounds__(256) void k_gemm_av(const float* __restrict__ V,
                                                 const float* __restrict__ att,
                                                 float* __restrict__ out) {
    int b = blockIdx.z;
    int m0 = blockIdx.y << 7;
    int n0 = blockIdx.x << 7;
    int nqp = PAD128(g_nq[b]);
    if (n0 >= nqp) return;
    int nkp = PAD128(g_nk[b]);
    __shared__ float As[16][128];
    __shared__ float Bs[16][128];
    const float* Ab = V + (long)b * CC * NN;
    const float* Bb = att + (long)b * NN * NN;
    int tid = threadIdx.x;
    int mb = (tid >> 4) << 3;
    int nb = (tid & 15) << 3;
    float acc[8][8];
#pragma unroll
    for (int i = 0; i < 8; i++)
#pragma unroll
        for (int j = 0; j < 8; j++) acc[i][j] = 0.f;

    for (int kc = 0; kc < nkp; kc += 16) {
#pragma unroll
        for (int t = 0; t < 2; t++) {
            int fid = tid + (t << 8);
            int rr = fid >> 2;
            int kb = (fid & 3) << 2;
            float4 av = *(const float4*)(Ab + (long)(m0 + rr) * NN + kc + kb);
            As[kb + 0][rr] = av.x; As[kb + 1][rr] = av.y;
            As[kb + 2][rr] = av.z; As[kb + 3][rr] = av.w;
            float4 bv = *(const float4*)(Bb + (long)(n0 + rr) * NN + kc + kb);
            Bs[kb + 0][rr] = bv.x; Bs[kb + 1][rr] = bv.y;
            Bs[kb + 2][rr] = bv.z; Bs[kb + 3][rr] = bv.w;
        }
        __syncthreads();
#pragma unroll
        for (int kk = 0; kk < 16; kk++) {
            float a[8], bb[8];
            *(float4*)&a[0] = *(float4*)&As[kk][mb];
            *(float4*)&a[4] = *(float4*)&As[kk][mb + 4];
            *(float4*)&bb[0] = *(float4*)&Bs[kk][nb];
            *(float4*)&bb[4] = *(float4*)&Bs[kk][nb + 4];
#pragma unroll
            for (int i = 0; i < 8; i++)
#pragma unroll
                for (int j = 0; j < 8; j++) acc[i][j] = fmaf(a[i], bb[j], acc[i][j]);
        }
        __syncthreads();
    }
    float* ob = out + (long)b * CC * NN;
#pragma unroll
    for (int i = 0; i < 8; i++) {
        long ro = (long)(m0 + mb + i) * NN + n0 + nb;
        *(float4*)(ob + ro) = *(float4*)&acc[i][0];
        *(float4*)(ob + ro + 4) = *(float4*)&acc[i][4];
    }
}

// ---------------- fuse 1x1 conv + scatter to output ------------------------
__global__ __launch_bounds__(256) void k_gemm_fuse(const float* __restrict__ wf,
                                                   const float* __restrict__ afore,
                                                   const float* __restrict__ xq,
                                                   float* __restrict__ out) {
    int b = blockIdx.z;
    int m0 = blockIdx.y << 7;   // co
    int n0 = blockIdx.x << 7;   // compacted query index
    int nq = g_nq[b];
    if (n0 >= PAD128(nq)) return;
    __shared__ float As[16][128];
    __shared__ float Bs[16][128];
    int tid = threadIdx.x;
    int mb = (tid >> 4) << 3;
    int nb = (tid & 15) << 3;
    float acc[8][8];
#pragma unroll
    for (int i = 0; i < 8; i++)
#pragma unroll
        for (int j = 0; j < 8; j++) acc[i][j] = 0.f;

    for (int kc = 0; kc < 2 * CC; kc += 16) {
#pragma unroll
        for (int t = 0; t < 2; t++) {
            int fid = tid + (t << 8);
            int rr = fid >> 2;
            int kb = (fid & 3) << 2;
            float4 av = *(const float4*)(wf + (long)(m0 + rr) * 512 + kc + kb);
            As[kb + 0][rr] = av.x; As[kb + 1][rr] = av.y;
            As[kb + 2][rr] = av.z; As[kb + 3][rr] = av.w;
            int row = fid >> 5;
            int col = (fid & 31) << 2;
            int kki = kc + row;
            const float* src = (kki < CC) ? (afore + (long)(b * CC + kki) * NN)
                                          : (xq + (long)(b * CC + kki - CC) * NN);
            *(float4*)&Bs[row][col] = *(const float4*)(src + n0 + col);
        }
        __syncthreads();
#pragma unroll
        for (int kk = 0; kk < 16; kk++) {
            float a[8], bb[8];
            *(float4*)&a[0] = *(float4*)&As[kk][mb];
            *(float4*)&a[4] = *(float4*)&As[kk][mb + 4];
            *(float4*)&bb[0] = *(float4*)&Bs[kk][nb];
            *(float4*)&bb[4] = *(float4*)&Bs[kk][nb + 4];
#pragma unroll
            for (int i = 0; i < 8; i++)
#pragma unroll
                for (int j = 0; j < 8; j++) acc[i][j] = fmaf(a[i], bb[j], acc[i][j]);
        }
        __syncthreads();
    }
    const int* qidx = g_qidx + (b << 12);
#pragma unroll
    for (int j = 0; j < 8; j++) {
        int i = n0 + nb + j;
        if (i < nq) {
            int px = qidx[i];
#pragma unroll
            for (int ii = 0; ii < 8; ii++) {
                int co = m0 + mb + ii;
                out[((b * CC + co) << 12) + px] = acc[ii][j];
            }
        }
    }
}

// ---------------- global max of visatt ----------------------------------
__global__ void k_vismax() {
    float mx = -1e30f;
    for (int i = threadIdx.x; i < BB * NN; i += 256) mx = fmaxf(mx, g_vis[i]);
    mx = warpMax(mx);
    __shared__ float sh[8];
    if ((threadIdx.x & 31) == 0) sh[threadIdx.x >> 5] = mx;
    __syncthreads();
    if (threadIdx.x == 0) {
        float m2 = sh[0];
#pragma unroll
        for (int i = 1; i < 8; i++) m2 = fmaxf(m2, sh[i]);
        g_maxv[0] = m2;
    }
}

// ---------------- attmask: 8x nearest upsample / max --------------------
__global__ void k_attmask(float* __restrict__ o) {
    int i = blockIdx.x * 256 + threadIdx.x;   // < 524288
    int b = i >> 18;
    int r = i & 262143;
    int Y = r >> 9, X = r & 511;
    o[i] = g_vis[(b << 12) + ((Y >> 3) << 6) + (X >> 3)] / g_maxv[0];
}

// ---------------- launch -------------------------------------------------
extern "C" void kernel_launch(void* const* d_in, const int* in_sizes, int n_in,
                              void* d_out, int out_size) {
    const float* x = nullptr;
    const float* mask = nullptr;
    const float* w1 = nullptr;
    const float* w2 = nullptr;
    const float* wf = nullptr;
    int seen589 = 0;
    for (int i = 0; i < n_in; i++) {
        switch (in_sizes[i]) {
            case 2097152: x = (const float*)d_in[i]; break;
            case 524288:  mask = (const float*)d_in[i]; break;
            case 589824:
                if (seen589++ == 0) w1 = (const float*)d_in[i];
                else w2 = (const float*)d_in[i];
                break;
            case 131072:  wf = (const float*)d_in[i]; break;
            default: break;
        }
    }

    float *bufA, *bufB, *Qc, *Kc, *Vc, *Xq, *att;
    cudaGetSymbolAddress((void**)&bufA, g_bufA);
    cudaGetSymbolAddress((void**)&bufB, g_bufB);
    cudaGetSymbolAddress((void**)&Qc, g_Qc);
    cudaGetSymbolAddress((void**)&Kc, g_Kc);
    cudaGetSymbolAddress((void**)&Vc, g_Vc);
    cudaGetSymbolAddress((void**)&Xq, g_Xq);
    cudaGetSymbolAddress((void**)&att, g_att);

    float* out = (float*)d_out;
    float* attm = out + (long)BB * CC * NN;

    // out = x everywhere (background default); fuse scatters valid pixels
    cudaMemcpyAsync(out, x, (size_t)BB * CC * NN * sizeof(float),
                    cudaMemcpyDeviceToDevice);

    k_mask<<<32, 256>>>(mask);
    k_compact<<<BB, 256>>>();
    k_conv3<<<dim3(16, 8, BB), 256>>>(x, w1, bufA);
    k_inorm<<<BB * CC, 256>>>(bufA, nullptr, bufB, 0);
    k_conv3<<<dim3(16, 8, BB), 256>>>(bufB, w2, bufA);
    k_inorm<<<BB * CC, 256>>>(bufA, x, bufB, 1);           // bufB = feat
    k_rn<<<32, 256>>>(bufB);
    k_gather<<<dim3(16, 2, BB), 256>>>(bufB, x);           // Qc,Xq,Kc,Vc
    k_gemm_score<<<dim3(32, 32, BB), 256>>>(Qc, Kc, att);
    k_softmax<<<dim3(4096, BB), 256>>>(att);
    k_visatt<<<dim3(64, BB), 256>>>(att);
    k_gemm_av<<<dim3(32, 2, BB), 256>>>(Vc, att, bufA);    // bufA = AFq
    k_vismax<<<1, 256>>>();
    k_gemm_fuse<<<dim3(32, 2, BB), 256>>>(wf, bufA, Xq, out);
    k_attmask<<<2048, 256>>>(attm);
}

// round 3
// speedup vs baseline: 1.8580x; 1.1228x over previous
#include <cuda_runtime.h>
#include <cuda_bf16.h>
#include <math.h>
#include <stdint.h>

#define BB 2
#define CC 256
#define HH 64
#define WW 64
#define NN 4096
#define EPS_IN 1e-5f
#define EPS_NORM 1e-8f
#define SCALE 20.0f
#define PAD128(v) (((v) + 127) & ~127)

// ---------------- static scratch ----------------
__device__ float g_m[BB * NN];
__device__ int   g_qidx[BB * NN];
__device__ int   g_kidx[BB * NN];
__device__ int   g_nq[BB];
__device__ int   g_nk[BB];
__device__ float g_bufA[BB * CC * NN];   // conv out fp32 / AFq
__device__ float g_bufB[BB * CC * NN];   // feat
__device__ float g_rn[BB * NN];
__device__ float g_Qc[BB * CC * NN];
__device__ float g_Kc[BB * CC * NN];
__device__ float g_Vc[BB * CC * NN];
__device__ float g_Xq[BB * CC * NN];
__device__ float g_att[(long)BB * NN * NN];
__device__ float g_vis[BB * NN];
__device__ float g_maxv[1];

// bf16 split inputs for tensor-core convs
__device__ __nv_bfloat16 g_xh[BB * CC * NN];
__device__ __nv_bfloat16 g_xl[BB * CC * NN];
__device__ __nv_bfloat16 g_f1h[BB * CC * NN];
__device__ __nv_bfloat16 g_f1l[BB * CC * NN];
// packed weights: [kappa 9][co 256][ci-pair 128] u32 = (bf16 even | bf16 odd << 16)
#define WPK (9 * 256 * 128)
__device__ uint32_t g_w1h[WPK];
__device__ uint32_t g_w1l[WPK];
__device__ uint32_t g_w2h[WPK];
__device__ uint32_t g_w2l[WPK];

__device__ __forceinline__ float warpMax(float v) {
#pragma unroll
    for (int o = 16; o; o >>= 1) v = fmaxf(v, __shfl_xor_sync(0xffffffffu, v, o));
    return v;
}
__device__ __forceinline__ float warpSum(float v) {
#pragma unroll
    for (int o = 16; o; o >>= 1) v += __shfl_xor_sync(0xffffffffu, v, o);
    return v;
}

__device__ __forceinline__ void mma_bf16(float c[4], const uint32_t a[4],
                                         uint32_t b0, uint32_t b1) {
    asm volatile(
        "mma.sync.aligned.m16n8k16.row.col.f32.bf16.bf16.f32 "
        "{%0,%1,%2,%3}, {%4,%5,%6,%7}, {%8,%9}, {%0,%1,%2,%3};"
        : "+f"(c[0]), "+f"(c[1]), "+f"(c[2]), "+f"(c[3])
        : "r"(a[0]), "r"(a[1]), "r"(a[2]), "r"(a[3]), "r"(b0), "r"(b1));
}

// ---------------- mask: MaxPool2d(8,8) > 0; also zero g_vis ---------------
__global__ void k_mask(const float* __restrict__ mask) {
    int gid = blockIdx.x * 256 + threadIdx.x;
    int b = gid >> 12;
    int j = gid & 4095;
    int py = j >> 6, px = j & 63;
    const float* mp = mask + (long)b * 262144 + (py * 8) * 512 + px * 8;
    float mx = 0.f;
#pragma unroll
    for (int dy = 0; dy < 8; dy++)
#pragma unroll
        for (int dx = 0; dx < 8; dx++) mx = fmaxf(mx, mp[dy * 512 + dx]);
    g_m[gid] = (mx > 0.f) ? 1.f : 0.f;
    g_vis[gid] = 0.f;
}

// ---------------- deterministic compaction --------------------------------
__global__ __launch_bounds__(256) void k_compact() {
    int b = blockIdx.x;
    int tid = threadIdx.x;
    __shared__ int wsum[8];
    __shared__ int baseq, basek;
    if (tid == 0) { baseq = 0; basek = 0; }
    __syncthreads();
    for (int chunk = 0; chunk < 16; chunk++) {
        int px = (chunk << 8) + tid;
        int vq = (g_m[(b << 12) + px] > 0.5f) ? 1 : 0;
        unsigned bal = __ballot_sync(0xffffffffu, vq);
        int lane = tid & 31, w = tid >> 5;
        int pre = __popc(bal & ((1u << lane) - 1u));
        if (lane == 0) wsum[w] = __popc(bal);
        __syncthreads();
        int woff = 0, tot = 0;
#pragma unroll
        for (int i = 0; i < 8; i++) {
            if (i < w) woff += wsum[i];
            tot += wsum[i];
        }
        int bq = baseq, bk = basek;
        int qbefore = woff + pre;
        if (vq) g_qidx[(b << 12) + bq + qbefore] = px;
        else    g_kidx[(b << 12) + bk + (tid - qbefore)] = px;
        __syncthreads();
        if (tid == 0) { baseq = bq + tot; basek = bk + (256 - tot); }
        __syncthreads();
    }
    if (tid == 0) { g_nq[b] = baseq; g_nk[b] = basek; }
}

// ---------------- pack weights: w[co][ci][3][3] -> [kap][co][cipair] ------
__global__ void k_packW(const float* __restrict__ w,
                        uint32_t* __restrict__ oh, uint32_t* __restrict__ ol) {
    int idx = blockIdx.x * 256 + threadIdx.x;   // < 294912
    int kap = idx >> 15;
    int rem = idx & 32767;
    int co = rem >> 7, cp = rem & 127;
    float v0 = w[(co * 256 + 2 * cp) * 9 + kap];
    float v1 = w[(co * 256 + 2 * cp + 1) * 9 + kap];
    __nv_bfloat16 h0 = __float2bfloat16(v0);
    __nv_bfloat16 l0 = __float2bfloat16(v0 - __bfloat162float(h0));
    __nv_bfloat16 h1 = __float2bfloat16(v1);
    __nv_bfloat16 l1 = __float2bfloat16(v1 - __bfloat162float(h1));
    oh[idx] = (uint32_t)__bfloat16_as_ushort(h0) |
              ((uint32_t)__bfloat16_as_ushort(h1) << 16);
    ol[idx] = (uint32_t)__bfloat16_as_ushort(l0) |
              ((uint32_t)__bfloat16_as_ushort(l1) << 16);
}

// ---------------- split x -> bf16 hi/lo ------------------------------------
__global__ void k_packX(const float* __restrict__ x,
                        __nv_bfloat16* __restrict__ xh,
                        __nv_bfloat16* __restrict__ xl) {
    int i = blockIdx.x * 256 + threadIdx.x;   // < 2097152
    float v = x[i];
    __nv_bfloat16 h = __float2bfloat16(v);
    xh[i] = h;
    xl[i] = __float2bfloat16(v - __bfloat162float(h));
}

// ---------------- tensor-core conv3x3: implicit GEMM ----------------------
// grid (64 y-rows, 2 co-tiles, BB); block 256 (8 warps = 4M x 2N)
// out[co][p] = sum_{ci,kap} W[co][ci][kap] * x[ci][shift_kap(p)]
__global__ __launch_bounds__(256) void k_conv_tc(const __nv_bfloat16* __restrict__ xh,
                                                 const __nv_bfloat16* __restrict__ xl,
                                                 const uint32_t* __restrict__ wph,
                                                 const uint32_t* __restrict__ wpl,
                                                 float* __restrict__ out) {
    __shared__ uint32_t sAh[2][128][12];
    __shared__ uint32_t sAl[2][128][12];
    __shared__ uint32_t sBh[1728];   // [3 imgrow][8 cipair][72 col]
    __shared__ uint32_t sBl[1728];

    int tid = threadIdx.x;
    int ytile = blockIdx.x;          // image row
    int co0 = blockIdx.y << 7;
    int b = blockIdx.z;
    int w = tid >> 5, l = tid & 31;
    int wm = w & 3, wn = w >> 2;
    int grp = l >> 2, tig = l & 3;

    float acc[2][4][4];
#pragma unroll
    for (int i = 0; i < 2; i++)
#pragma unroll
        for (int j = 0; j < 4; j++)
#pragma unroll
            for (int k = 0; k < 4; k++) acc[i][j][k] = 0.f;

    long xbase = (long)b * CC * NN;
    int buf = 0;

    for (int chunk = 0; chunk < 16; chunk++) {
        int ci0 = chunk << 4;
        // ---- stage B: x halo tile, pair-packed along ci ----
        for (int tsk = tid; tsk < 384; tsk += 256) {
            int srow = tsk >> 7;          // 0..2
            int rem = tsk & 127;
            int pair = rem >> 4, cg = rem & 15;
            int gy = ytile - 1 + srow;
            int sb = (srow * 8 + pair) * 72 + 1 + (cg << 2);
            if ((unsigned)gy < 64u) {
                long e = xbase + (long)(ci0 + (pair << 1)) * NN + (gy << 6) + (cg << 2);
                long o = e + NN;
                uint32_t e0 = *(const uint32_t*)(xh + e);
                uint32_t e1 = *(const uint32_t*)(xh + e + 2);
                uint32_t o0 = *(const uint32_t*)(xh + o);
                uint32_t o1 = *(const uint32_t*)(xh + o + 2);
                sBh[sb + 0] = __byte_perm(e0, o0, 0x5410);
                sBh[sb + 1] = __byte_perm(e0, o0, 0x7632);
                sBh[sb + 2] = __byte_perm(e1, o1, 0x5410);
                sBh[sb + 3] = __byte_perm(e1, o1, 0x7632);
                e0 = *(const uint32_t*)(xl + e);
                e1 = *(const uint32_t*)(xl + e + 2);
                o0 = *(const uint32_t*)(xl + o);
                o1 = *(const uint32_t*)(xl + o + 2);
                sBl[sb + 0] = __byte_perm(e0, o0, 0x5410);
                sBl[sb + 1] = __byte_perm(e0, o0, 0x7632);
                sBl[sb + 2] = __byte_perm(e1, o1, 0x5410);
                sBl[sb + 3] = __byte_perm(e1, o1, 0x7632);
            } else {
#pragma unroll
                for (int z = 0; z < 4; z++) { sBh[sb + z] = 0; sBl[sb + z] = 0; }
            }
        }
        if (tid < 48) {   // zero edge columns (image col -1 and 64)
            int srow = tid / 16, rem = tid % 16;
            int pair = rem >> 1, edge = rem & 1;
            int off = (srow * 8 + pair) * 72 + (edge ? 65 : 0);
            sBh[off] = 0;
            sBl[off] = 0;
        }
        // ---- stage A kap=0 ----
        {
            long wb = (long)co0 * 128 + (chunk << 3);
            for (int idx = tid; idx < 1024; idx += 256) {
                int row = idx >> 3, col = idx & 7;
                sAh[buf][row][col] = wph[wb + row * 128 + col];
                sAl[buf][row][col] = wpl[wb + row * 128 + col];
            }
        }
        __syncthreads();

        for (int kap = 0; kap < 9; kap++) {
            if (kap < 8) {   // prefetch next A into other buffer
                long wb = (long)((kap + 1) * 256 + co0) * 128 + (chunk << 3);
                for (int idx = tid; idx < 1024; idx += 256) {
                    int row = idx >> 3, col = idx & 7;
                    sAh[buf ^ 1][row][col] = wph[wb + row * 128 + col];
                    sAl[buf ^ 1][row][col] = wpl[wb + row * 128 + col];
                }
            }
            int dy = kap / 3, dx = kap - dy * 3;   // 0..2 each
            uint32_t ah[2][4], al[2][4];
#pragma unroll
            for (int mf = 0; mf < 2; mf++) {
                int mr = (wm << 5) + (mf << 4);
                ah[mf][0] = sAh[buf][mr + grp][tig];
                ah[mf][1] = sAh[buf][mr + grp + 8][tig];
                ah[mf][2] = sAh[buf][mr + grp][tig + 4];
                ah[mf][3] = sAh[buf][mr + grp + 8][tig + 4];
                al[mf][0] = sAl[buf][mr + grp][tig];
                al[mf][1] = sAl[buf][mr + grp + 8][tig];
                al[mf][2] = sAl[buf][mr + grp][tig + 4];
                al[mf][3] = sAl[buf][mr + grp + 8][tig + 4];
            }
#pragma unroll
            for (int nf = 0; nf < 4; nf++) {
                int n = (wn << 5) + (nf << 3) + grp;   // pixel col
                int a0 = (dy * 8 + tig) * 72 + n + dx;
                uint32_t bh0 = sBh[a0];
                uint32_t bh1 = sBh[a0 + 288];   // pair + 4
                uint32_t bl0 = sBl[a0];
                uint32_t bl1 = sBl[a0 + 288];
#pragma unroll
                for (int mf = 0; mf < 2; mf++) {
                    mma_bf16(acc[mf][nf], ah[mf], bh0, bh1);
                    mma_bf16(acc[mf][nf], ah[mf], bl0, bl1);
                    mma_bf16(acc[mf][nf], al[mf], bh0, bh1);
                }
            }
            __syncthreads();
            buf ^= 1;
        }
    }
    // ---- epilogue ----
#pragma unroll
    for (int mf = 0; mf < 2; mf++) {
        int r0 = co0 + (wm << 5) + (mf << 4) + grp;
#pragma unroll
        for (int nf = 0; nf < 4; nf++) {
            int p = (ytile << 6) + (wn << 5) + (nf << 3) + (tig << 1);
            float2 v0 = make_float2(acc[mf][nf][0], acc[mf][nf][1]);
            float2 v1 = make_float2(acc[mf][nf][2], acc[mf][nf][3]);
            *(float2*)&out[((long)(b * CC + r0) << 12) + p] = v0;
            *(float2*)&out[((long)(b * CC + r0 + 8) << 12) + p] = v1;
        }
    }
}

// ---------------- instance norm + relu -> bf16 split (after conv1) --------
__global__ __launch_bounds__(256) void k_inorm0(const float* __restrict__ t,
                                                __nv_bfloat16* __restrict__ oh,
                                                __nv_bfloat16* __restrict__ ol) {
    long base = (long)blockIdx.x * NN;
    int tid = threadIdx.x;
    float s = 0.f, s2 = 0.f;
    for (int i = tid; i < NN; i += 256) {
        float v = t[base + i];
        s += v;
        s2 = fmaf(v, v, s2);
    }
    __shared__ float sh[16];
    __shared__ float smu, srs;
    s = warpSum(s);
    s2 = warpSum(s2);
    int wi = tid >> 5, l = tid & 31;
    if (l == 0) { sh[wi] = s; sh[8 + wi] = s2; }
    __syncthreads();
    if (tid == 0) {
        float a = 0.f, b2 = 0.f;
#pragma unroll
        for (int i = 0; i < 8; i++) { a += sh[i]; b2 += sh[8 + i]; }
        float mu = a * (1.f / NN);
        float var = b2 * (1.f / NN) - mu * mu;
        smu = mu;
        srs = rsqrtf(var + EPS_IN);
    }
    __syncthreads();
    float mu = smu, rs = srs;
    for (int i = tid; i < NN; i += 256) {
        float v = fmaxf((t[base + i] - mu) * rs, 0.f);
        __nv_bfloat16 h = __float2bfloat16(v);
        oh[base + i] = h;
        ol[base + i] = __float2bfloat16(v - __bfloat162float(h));
    }
}

// ---------------- instance norm + residual + relu -> fp32 (after conv2) ---
__global__ __launch_bounds__(256) void k_inorm1(const float* __restrict__ t,
                                                const float* __restrict__ xadd,
                                                float* __restrict__ o) {
    long base = (long)blockIdx.x * NN;
    int tid = threadIdx.x;
    float s = 0.f, s2 = 0.f;
    for (int i = tid; i < NN; i += 256) {
        float v = t[base + i];
        s += v;
        s2 = fmaf(v, v, s2);
    }
    __shared__ float sh[16];
    __shared__ float smu, srs;
    s = warpSum(s);
    s2 = warpSum(s2);
    int wi = tid >> 5, l = tid & 31;
    if (l == 0) { sh[wi] = s; sh[8 + wi] = s2; }
    __syncthreads();
    if (tid == 0) {
        float a = 0.f, b2 = 0.f;
#pragma unroll
        for (int i = 0; i < 8; i++) { a += sh[i]; b2 += sh[8 + i]; }
        float mu = a * (1.f / NN);
        float var = b2 * (1.f / NN) - mu * mu;
        smu = mu;
        srs = rsqrtf(var + EPS_IN);
    }
    __syncthreads();
    float mu = smu, rs = srs;
    for (int i = tid; i < NN; i += 256)
        o[base + i] = fmaxf((t[base + i] - mu) * rs + xadd[base + i], 0.f);
}

// ---------------- per-pixel channel L2 norm reciprocal --------------------
__global__ void k_rn(const float* __restrict__ feat) {
    int gid = blockIdx.x * 256 + threadIdx.x;
    int b = gid >> 12;
    int px = gid & 4095;
    const float* fb = feat + (long)b * CC * NN + px;
    float s = 0.f;
    for (int c = 0; c < CC; c++) {
        float f = fb[c << 12];
        s = fmaf(f, f, s);
    }
    g_rn[gid] = 1.f / (sqrtf(s) + EPS_NORM);
}

// ---------------- gather compacted matrices -------------------------------
__global__ __launch_bounds__(256) void k_gather(const float* __restrict__ feat,
                                                const float* __restrict__ x) {
    int b = blockIdx.z;
    int side = blockIdx.y;
    int i = (blockIdx.x << 8) + threadIdx.x;
    int n = side ? g_nk[b] : g_nq[b];
    int npad = PAD128(n);
    if (i >= npad) return;
    float* A = side ? g_Kc : g_Qc;
    float* B2 = side ? g_Vc : g_Xq;
    long off = (long)b * CC * NN;
    if (i < n) {
        int px = side ? g_kidx[(b << 12) + i] : g_qidx[(b << 12) + i];
        float rn = g_rn[(b << 12) + px];
        const float* fb = feat + off + px;
        const float* xb = x + off + px;
        for (int c = 0; c < CC; c++) {
            A[off + (c << 12) + i] = fb[c << 12] * rn;
            B2[off + (c << 12) + i] = xb[c << 12];
        }
    } else {
        for (int c = 0; c < CC; c++) {
            A[off + (c << 12) + i] = 0.f;
            B2[off + (c << 12) + i] = 0.f;
        }
    }
}

// ---------------- score GEMM (compacted): 128x128x16 ----------------------
__global__ __launch_bounds__(256) void k_gemm_score(const float* __restrict__ Q,
                                                    const float* __restrict__ K,
                                                    float* __restrict__ att) {
    int b = blockIdx.z;
    int q0 = blockIdx.y << 7;
    int k0 = blockIdx.x << 7;
    if (q0 >= PAD128(g_nq[b]) || k0 >= PAD128(g_nk[b])) return;
    __shared__ float As[16][128];
    __shared__ float Bs[16][128];
    const float* Ab = Q + (long)b * CC * NN;
    const float* Bb = K + (long)b * CC * NN;
    float* Cb = att + (long)b * NN * NN;
    int tid = threadIdx.x;
    int mb = (tid >> 4) << 3;
    int nb = (tid & 15) << 3;
    float acc[8][8];
#pragma unroll
    for (int i = 0; i < 8; i++)
#pragma unroll
        for (int j = 0; j < 8; j++) acc[i][j] = 0.f;

    for (int c0 = 0; c0 < CC; c0 += 16) {
#pragma unroll
        for (int t = 0; t < 2; t++) {
            int idx = tid + (t << 8);
            int row = idx >> 5;
            int col = (idx & 31) << 2;
            *(float4*)&As[row][col] = *(const float4*)(Ab + (long)(c0 + row) * NN + q0 + col);
            *(float4*)&Bs[row][col] = *(const float4*)(Bb + (long)(c0 + row) * NN + k0 + col);
        }
        __syncthreads();
#pragma unroll
        for (int kk = 0; kk < 16; kk++) {
            float a[8], bb[8];
            *(float4*)&a[0] = *(float4*)&As[kk][mb];
            *(float4*)&a[4] = *(float4*)&As[kk][mb + 4];
            *(float4*)&bb[0] = *(float4*)&Bs[kk][nb];
            *(float4*)&bb[4] = *(float4*)&Bs[kk][nb + 4];
#pragma unroll
            for (int i = 0; i < 8; i++)
#pragma unroll
                for (int j = 0; j < 8; j++) acc[i][j] = fmaf(a[i], bb[j], acc[i][j]);
        }
        __syncthreads();
    }
#pragma unroll
    for (int i = 0; i < 8; i++) {
        long ro = (long)(q0 + mb + i) * NN + k0 + nb;
        float4 o0, o1;
        o0.x = acc[i][0] * SCALE; o0.y = acc[i][1] * SCALE;
        o0.z = acc[i][2] * SCALE; o0.w = acc[i][3] * SCALE;
        o1.x = acc[i][4] * SCALE; o1.y = acc[i][5] * SCALE;
        o1.z = acc[i][6] * SCALE; o1.w = acc[i][7] * SCALE;
        *(float4*)(Cb + ro) = o0;
        *(float4*)(Cb + ro + 4) = o1;
    }
}

// ---------------- softmax over compacted keys ------------------------------
__global__ __launch_bounds__(256) void k_softmax(float* __restrict__ att) {
    int b = blockIdx.y;
    int i = blockIdx.x;
    int nq = g_nq[b];
    if (i >= nq) return;
    int nk = g_nk[b];
    int nkp = PAD128(nk);
    float* row = att + (long)b * NN * NN + (long)i * NN;
    int tid = threadIdx.x;
    float vals[16];
    float mx = -1e30f;
    int nt = (nkp + 255) >> 8;
#pragma unroll
    for (int t = 0; t < 16; t++) {
        if (t >= nt) break;
        int k = tid + (t << 8);
        float s = (k < nk) ? row[k] : -1e30f;
        vals[t] = s;
        mx = fmaxf(mx, s);
    }
    __shared__ float sh[8];
    __shared__ float bval;
    mx = warpMax(mx);
    int wi = tid >> 5, l = tid & 31;
    if (l == 0) sh[wi] = mx;
    __syncthreads();
    if (tid == 0) {
        float m2 = sh[0];
#pragma unroll
        for (int ii = 1; ii < 8; ii++) m2 = fmaxf(m2, sh[ii]);
        bval = m2;
    }
    __syncthreads();
    mx = bval;
    float sum = 0.f;
#pragma unroll
    for (int t = 0; t < 16; t++) {
        if (t >= nt) break;
        float e = __expf(vals[t] - mx);
        vals[t] = e;
        sum += e;
    }
    sum = warpSum(sum);
    __syncthreads();
    if (l == 0) sh[wi] = sum;
    __syncthreads();
    if (tid == 0) {
        float s2 = 0.f;
#pragma unroll
        for (int ii = 0; ii < 8; ii++) s2 += sh[ii];
        bval = 1.f / s2;
    }
    __syncthreads();
    float rinv = bval;
#pragma unroll
    for (int t = 0; t < 16; t++) {
        if (t >= nt) break;
        int k = tid + (t << 8);
        row[k] = (k < nk) ? vals[t] * rinv : 0.f;
    }
}

// ---------------- visatt: column sums of compacted att, scattered ---------
__global__ void k_visatt(const float* __restrict__ att) {
    int b = blockIdx.y;
    int k0 = blockIdx.x << 6;
    int nk = g_nk[b];
    if (k0 >= nk) return;
    int nq = g_nq[b];
    int kk = threadIdx.x & 63;
    int qq = threadIdx.x >> 6;
    const float* base = att + (long)b * NN * NN + k0 + kk;
    float s = 0.f;
    for (int q = qq; q < nq; q += 4) s += base[(long)q << 12];
    __shared__ float sh[256];
    sh[threadIdx.x] = s;
    __syncthreads();
    if (threadIdx.x < 64) {
        int k = k0 + threadIdx.x;
        if (k < nk) {
            float tot = sh[threadIdx.x] + sh[threadIdx.x + 64] +
                        sh[threadIdx.x + 128] + sh[threadIdx.x + 192];
            g_vis[(b << 12) + g_kidx[(b << 12) + k]] = tot;
        }
    }
}

// ---------------- AV GEMM ---------------------------------------------------
__global__ __launch_bounds__(256) void k_gemm_av(const float* __restrict__ V,
                                                 const float* __restrict__ att,
                                                 float* __restrict__ out) {
    int b = blockIdx.z;
    int m0 = blockIdx.y << 7;
    int n0 = blockIdx.x << 7;
    int nqp = PAD128(g_nq[b]);
    if (n0 >= nqp) return;
    int nkp = PAD128(g_nk[b]);
    __shared__ float As[16][128];
    __shared__ float Bs[16][128];
    const float* Ab = V + (long)b * CC * NN;
    const float* Bb = att + (long)b * NN * NN;
    int tid = threadIdx.x;
    int mb = (tid >> 4) << 3;
    int nb = (tid & 15) << 3;
    float acc[8][8];
#pragma unroll
    for (int i = 0; i < 8; i++)
#pragma unroll
        for (int j = 0; j < 8; j++) acc[i][j] = 0.f;

    for (int kc = 0; kc < nkp; kc += 16) {
#pragma unroll
        for (int t = 0; t < 2; t++) {
            int fid = tid + (t << 8);
            int rr = fid >> 2;
            int kb = (fid & 3) << 2;
            float4 av = *(const float4*)(Ab + (long)(m0 + rr) * NN + kc + kb);
            As[kb + 0][rr] = av.x; As[kb + 1][rr] = av.y;
            As[kb + 2][rr] = av.z; As[kb + 3][rr] = av.w;
            float4 bv = *(const float4*)(Bb + (long)(n0 + rr) * NN + kc + kb);
            Bs[kb + 0][rr] = bv.x; Bs[kb + 1][rr] = bv.y;
            Bs[kb + 2][rr] = bv.z; Bs[kb + 3][rr] = bv.w;
        }
        __syncthreads();
#pragma unroll
        for (int kk = 0; kk < 16; kk++) {
            float a[8], bb[8];
            *(float4*)&a[0] = *(float4*)&As[kk][mb];
            *(float4*)&a[4] = *(float4*)&As[kk][mb + 4];
            *(float4*)&bb[0] = *(float4*)&Bs[kk][nb];
            *(float4*)&bb[4] = *(float4*)&Bs[kk][nb + 4];
#pragma unroll
            for (int i = 0; i < 8; i++)
#pragma unroll
                for (int j = 0; j < 8; j++) acc[i][j] = fmaf(a[i], bb[j], acc[i][j]);
        }
        __syncthreads();
    }
    float* ob = out + (long)b * CC * NN;
#pragma unroll
    for (int i = 0; i < 8; i++) {
        long ro = (long)(m0 + mb + i) * NN + n0 + nb;
        *(float4*)(ob + ro) = *(float4*)&acc[i][0];
        *(float4*)(ob + ro + 4) = *(float4*)&acc[i][4];
    }
}

// ---------------- fuse 1x1 conv + scatter ----------------------------------
__global__ __launch_bounds__(256) void k_gemm_fuse(const float* __restrict__ wf,
                                                   const float* __restrict__ afore,
                                                   const float* __restrict__ xq,
                                                   float* __restrict__ out) {
    int b = blockIdx.z;
    int m0 = blockIdx.y << 7;
    int n0 = blockIdx.x << 7;
    int nq = g_nq[b];
    if (n0 >= PAD128(nq)) return;
    __shared__ float As[16][128];
    __shared__ float Bs[16][128];
    int tid = threadIdx.x;
    int mb = (tid >> 4) << 3;
    int nb = (tid & 15) << 3;
    float acc[8][8];
#pragma unroll
    for (int i = 0; i < 8; i++)
#pragma unroll
        for (int j = 0; j < 8; j++) acc[i][j] = 0.f;

    for (int kc = 0; kc < 2 * CC; kc += 16) {
#pragma unroll
        for (int t = 0; t < 2; t++) {
            int fid = tid + (t << 8);
            int rr = fid >> 2;
            int kb = (fid & 3) << 2;
            float4 av = *(const float4*)(wf + (long)(m0 + rr) * 512 + kc + kb);
            As[kb + 0][rr] = av.x; As[kb + 1][rr] = av.y;
            As[kb + 2][rr] = av.z; As[kb + 3][rr] = av.w;
            int row = fid >> 5;
            int col = (fid & 31) << 2;
            int kki = kc + row;
            const float* src = (kki < CC) ? (afore + (long)(b * CC + kki) * NN)
                                          : (xq + (long)(b * CC + kki - CC) * NN);
            *(float4*)&Bs[row][col] = *(const float4*)(src + n0 + col);
        }
        __syncthreads();
#pragma unroll
        for (int kk = 0; kk < 16; kk++) {
            float a[8], bb[8];
            *(float4*)&a[0] = *(float4*)&As[kk][mb];
            *(float4*)&a[4] = *(float4*)&As[kk][mb + 4];
            *(float4*)&bb[0] = *(float4*)&Bs[kk][nb];
            *(float4*)&bb[4] = *(float4*)&Bs[kk][nb + 4];
#pragma unroll
            for (int i = 0; i < 8; i++)
#pragma unroll
                for (int j = 0; j < 8; j++) acc[i][j] = fmaf(a[i], bb[j], acc[i][j]);
        }
        __syncthreads();
    }
    const int* qidx = g_qidx + (b << 12);
#pragma unroll
    for (int j = 0; j < 8; j++) {
        int i = n0 + nb + j;
        if (i < nq) {
            int px = qidx[i];
#pragma unroll
            for (int ii = 0; ii < 8; ii++) {
                int co = m0 + mb + ii;
                out[((b * CC + co) << 12) + px] = acc[ii][j];
            }
        }
    }
}

// ---------------- global max of visatt ----------------------------------
__global__ void k_vismax() {
    float mx = -1e30f;
    for (int i = threadIdx.x; i < BB * NN; i += 256) mx = fmaxf(mx, g_vis[i]);
    mx = warpMax(mx);
    __shared__ float sh[8];
    if ((threadIdx.x & 31) == 0) sh[threadIdx.x >> 5] = mx;
    __syncthreads();
    if (threadIdx.x == 0) {
        float m2 = sh[0];
#pragma unroll
        for (int i = 1; i < 8; i++) m2 = fmaxf(m2, sh[i]);
        g_maxv[0] = m2;
    }
}

// ---------------- attmask --------------------------------------------------
__global__ void k_attmask(float* __restrict__ o) {
    int i = blockIdx.x * 256 + threadIdx.x;
    int b = i >> 18;
    int r = i & 262143;
    int Y = r >> 9, X = r & 511;
    o[i] = g_vis[(b << 12) + ((Y >> 3) << 6) + (X >> 3)] / g_maxv[0];
}

// ---------------- launch -------------------------------------------------
extern "C" void kernel_launch(void* const* d_in, const int* in_sizes, int n_in,
                              void* d_out, int out_size) {
    const float* x = nullptr;
    const float* mask = nullptr;
    const float* w1 = nullptr;
    const float* w2 = nullptr;
    const float* wf = nullptr;
    int seen589 = 0;
    for (int i = 0; i < n_in; i++) {
        switch (in_sizes[i]) {
            case 2097152: x = (const float*)d_in[i]; break;
            case 524288:  mask = (const float*)d_in[i]; break;
            case 589824:
                if (seen589++ == 0) w1 = (const float*)d_in[i];
                else w2 = (const float*)d_in[i];
                break;
            case 131072:  wf = (const float*)d_in[i]; break;
            default: break;
        }
    }

    float *bufA, *bufB, *Qc, *Kc, *Vc, *Xq, *att;
    __nv_bfloat16 *xh, *xl, *f1h, *f1l;
    uint32_t *w1h, *w1l, *w2h, *w2l;
    cudaGetSymbolAddress((void**)&bufA, g_bufA);
    cudaGetSymbolAddress((void**)&bufB, g_bufB);
    cudaGetSymbolAddress((void**)&Qc, g_Qc);
    cudaGetSymbolAddress((void**)&Kc, g_Kc);
    cudaGetSymbolAddress((void**)&Vc, g_Vc);
    cudaGetSymbolAddress((void**)&Xq, g_Xq);
    cudaGetSymbolAddress((void**)&att, g_att);
    cudaGetSymbolAddress((void**)&xh, g_xh);
    cudaGetSymbolAddress((void**)&xl, g_xl);
    cudaGetSymbolAddress((void**)&f1h, g_f1h);
    cudaGetSymbolAddress((void**)&f1l, g_f1l);
    cudaGetSymbolAddress((void**)&w1h, g_w1h);
    cudaGetSymbolAddress((void**)&w1l, g_w1l);
    cudaGetSymbolAddress((void**)&w2h, g_w2h);
    cudaGetSymbolAddress((void**)&w2l, g_w2l);

    float* out = (float*)d_out;
    float* attm = out + (long)BB * CC * NN;

    cudaMemcpyAsync(out, x, (size_t)BB * CC * NN * sizeof(float),
                    cudaMemcpyDeviceToDevice);

    k_mask<<<32, 256>>>(mask);
    k_compact<<<BB, 256>>>();
    k_packW<<<1152, 256>>>(w1, w1h, w1l);
    k_packW<<<1152, 256>>>(w2, w2h, w2l);
    k_packX<<<8192, 256>>>(x, xh, xl);
    k_conv_tc<<<dim3(64, 2, BB), 256>>>(xh, xl, w1h, w1l, bufA);
    k_inorm0<<<BB * CC, 256>>>(bufA, f1h, f1l);
    k_conv_tc<<<dim3(64, 2, BB), 256>>>(f1h, f1l, w2h, w2l, bufA);
    k_inorm1<<<BB * CC, 256>>>(bufA, x, bufB);            // bufB = feat
    k_rn<<<32, 256>>>(bufB);
    k_gather<<<dim3(16, 2, BB), 256>>>(bufB, x);
    k_gemm_score<<<dim3(32, 32, BB), 256>>>(Qc, Kc, att);
    k_softmax<<<dim3(4096, BB), 256>>>(att);
    k_visatt<<<dim3(64, BB), 256>>>(att);
    k_gemm_av<<<dim3(32, 2, BB), 256>>>(Vc, att, bufA);
    k_vismax<<<1, 256>>>();
    k_gemm_fuse<<<dim3(32, 2, BB), 256>>>(wf, bufA, Xq, out);
    k_attmask<<<2048, 256>>>(attm);
}

// round 4
// speedup vs baseline: 2.7247x; 1.4665x over previous
#include <cuda_runtime.h>
#include <cuda_bf16.h>
#include <math.h>
#include <stdint.h>

#define BB 2
#define CC 256
#define NN 4096
#define EPS_IN 1e-5f
#define EPS_NORM 1e-8f
#define SCALE 20.0f
#define PAD128(v) (((v) + 127) & ~127)

// ---------------- static scratch ----------------
__device__ float g_m[BB * NN];
__device__ int   g_qidx[BB * NN];
__device__ int   g_kidx[BB * NN];
__device__ int   g_nq[BB];
__device__ int   g_nk[BB];
__device__ float g_bufA[BB * CC * NN];   // conv out fp32 / AFq
__device__ float g_bufB[BB * CC * NN];   // feat
__device__ float g_rn[BB * NN];
__device__ float g_Vc[BB * CC * NN];
__device__ float g_Xq[BB * CC * NN];
__device__ float g_att[(long)BB * NN * NN];
__device__ float g_vis[BB * NN];
__device__ float g_maxv[1];

// bf16 split inputs for tensor-core convs
__device__ __nv_bfloat16 g_xh[BB * CC * NN];
__device__ __nv_bfloat16 g_xl[BB * CC * NN];
__device__ __nv_bfloat16 g_f1h[BB * CC * NN];
__device__ __nv_bfloat16 g_f1l[BB * CC * NN];
// packed conv weights: [chunk 16][kap 9][co 256][cipair-in-chunk 8] u32
#define WPK (16 * 9 * 256 * 8)
__device__ uint32_t g_w1h[WPK];
__device__ uint32_t g_w1l[WPK];
__device__ uint32_t g_w2h[WPK];
__device__ uint32_t g_w2l[WPK];

// packed Q/K: [b][cp 128][i 4096] u32 (pair along c)
__device__ uint32_t g_Qph[BB * 128 * NN];
__device__ uint32_t g_Qpl[BB * 128 * NN];
__device__ uint32_t g_Kph[BB * 128 * NN];
__device__ uint32_t g_Kpl[BB * 128 * NN];
// packed V: [b][c 256][jp 2048] u32 (pair along j)
__device__ uint32_t g_Vph[BB * 256 * 2048];
__device__ uint32_t g_Vpl[BB * 256 * 2048];
// packed P: [b][i 4096][jp 2048] u32 (pair along j)
__device__ uint32_t g_Pph[(long)BB * NN * 2048];
__device__ uint32_t g_Ppl[(long)BB * NN * 2048];

__device__ __forceinline__ float warpMax(float v) {
#pragma unroll
    for (int o = 16; o; o >>= 1) v = fmaxf(v, __shfl_xor_sync(0xffffffffu, v, o));
    return v;
}
__device__ __forceinline__ float warpSum(float v) {
#pragma unroll
    for (int o = 16; o; o >>= 1) v += __shfl_xor_sync(0xffffffffu, v, o);
    return v;
}

__device__ __forceinline__ void mma_bf16(float c[4], const uint32_t a[4],
                                         uint32_t b0, uint32_t b1) {
    asm volatile(
        "mma.sync.aligned.m16n8k16.row.col.f32.bf16.bf16.f32 "
        "{%0,%1,%2,%3}, {%4,%5,%6,%7}, {%8,%9}, {%0,%1,%2,%3};"
        : "+f"(c[0]), "+f"(c[1]), "+f"(c[2]), "+f"(c[3])
        : "r"(a[0]), "r"(a[1]), "r"(a[2]), "r"(a[3]), "r"(b0), "r"(b1));
}

__device__ __forceinline__ uint32_t pack2bf(float v0, float v1) {
    __nv_bfloat16 h0 = __float2bfloat16(v0);
    __nv_bfloat16 h1 = __float2bfloat16(v1);
    return (uint32_t)__bfloat16_as_ushort(h0) |
           ((uint32_t)__bfloat16_as_ushort(h1) << 16);
}

// ---------------- mask: MaxPool2d(8,8) > 0; also zero g_vis ---------------
__global__ void k_mask(const float* __restrict__ mask) {
    int gid = blockIdx.x * 256 + threadIdx.x;
    int b = gid >> 12;
    int j = gid & 4095;
    int py = j >> 6, px = j & 63;
    const float* mp = mask + (long)b * 262144 + (py * 8) * 512 + px * 8;
    float mx = 0.f;
#pragma unroll
    for (int dy = 0; dy < 8; dy++)
#pragma unroll
        for (int dx = 0; dx < 8; dx++) mx = fmaxf(mx, mp[dy * 512 + dx]);
    g_m[gid] = (mx > 0.f) ? 1.f : 0.f;
    g_vis[gid] = 0.f;
}

// ---------------- deterministic compaction --------------------------------
__global__ __launch_bounds__(256) void k_compact() {
    int b = blockIdx.x;
    int tid = threadIdx.x;
    __shared__ int wsum[8];
    __shared__ int baseq, basek;
    if (tid == 0) { baseq = 0; basek = 0; }
    __syncthreads();
    for (int chunk = 0; chunk < 16; chunk++) {
        int px = (chunk << 8) + tid;
        int vq = (g_m[(b << 12) + px] > 0.5f) ? 1 : 0;
        unsigned bal = __ballot_sync(0xffffffffu, vq);
        int lane = tid & 31, w = tid >> 5;
        int pre = __popc(bal & ((1u << lane) - 1u));
        if (lane == 0) wsum[w] = __popc(bal);
        __syncthreads();
        int woff = 0, tot = 0;
#pragma unroll
        for (int i = 0; i < 8; i++) {
            if (i < w) woff += wsum[i];
            tot += wsum[i];
        }
        int bq = baseq, bk = basek;
        int qbefore = woff + pre;
        if (vq) g_qidx[(b << 12) + bq + qbefore] = px;
        else    g_kidx[(b << 12) + bk + (tid - qbefore)] = px;
        __syncthreads();
        if (tid == 0) { baseq = bq + tot; basek = bk + (256 - tot); }
        __syncthreads();
    }
    if (tid == 0) { g_nq[b] = baseq; g_nk[b] = basek; }
}

// ---------------- pack weights: w[co][ci][3][3] -> [chunk][kap][co][cpw] ---
__global__ void k_packW(const float* __restrict__ w,
                        uint32_t* __restrict__ oh, uint32_t* __restrict__ ol) {
    int idx = blockIdx.x * 256 + threadIdx.x;   // < 294912
    int cpw = idx & 7;
    int co = (idx >> 3) & 255;
    int t = idx >> 11;          // chunk*9 + kap
    int chunk = t / 9;
    int kap = t - chunk * 9;
    int cp = (chunk << 3) + cpw;
    float v0 = w[(co * 256 + 2 * cp) * 9 + kap];
    float v1 = w[(co * 256 + 2 * cp + 1) * 9 + kap];
    __nv_bfloat16 h0 = __float2bfloat16(v0);
    __nv_bfloat16 h1 = __float2bfloat16(v1);
    oh[idx] = pack2bf(v0, v1);
    ol[idx] = pack2bf(v0 - __bfloat162float(h0), v1 - __bfloat162float(h1));
}

// ---------------- split x -> bf16 hi/lo ------------------------------------
__global__ void k_packX(const float* __restrict__ x,
                        __nv_bfloat16* __restrict__ xh,
                        __nv_bfloat16* __restrict__ xl) {
    int i = blockIdx.x * 256 + threadIdx.x;
    float v = x[i];
    __nv_bfloat16 h = __float2bfloat16(v);
    xh[i] = h;
    xl[i] = __float2bfloat16(v - __bfloat162float(h));
}

// ---------------- tensor-core conv3x3: implicit GEMM ----------------------
// grid (64 y-rows, 2 co-tiles, BB); block 256 (8 warps = 4M x 2N)
// dynamic smem: sAh[9*128*9] sAl[...] sBh[1728] sBl[1728]
__global__ __launch_bounds__(256) void k_conv_tc(const __nv_bfloat16* __restrict__ xh,
                                                 const __nv_bfloat16* __restrict__ xl,
                                                 const uint32_t* __restrict__ wph,
                                                 const uint32_t* __restrict__ wpl,
                                                 float* __restrict__ out) {
    extern __shared__ uint32_t dsm[];
    uint32_t* sAh = dsm;                 // 9*128*9 = 10368
    uint32_t* sAl = sAh + 10368;
    uint32_t* sBh = sAl + 10368;         // 1728 = 24 rows * 72
    uint32_t* sBl = sBh + 1728;

    int tid = threadIdx.x;
    int ytile = blockIdx.x;
    int co0 = blockIdx.y << 7;
    int b = blockIdx.z;
    int w = tid >> 5, l = tid & 31;
    int wm = w & 3, wn = w >> 2;
    int grp = l >> 2, tig = l & 3;

    float acc[2][4][4];
#pragma unroll
    for (int i = 0; i < 2; i++)
#pragma unroll
        for (int j = 0; j < 4; j++)
#pragma unroll
            for (int k = 0; k < 4; k++) acc[i][j][k] = 0.f;

    long xbase = (long)b * CC * NN;

    for (int chunk = 0; chunk < 16; chunk++) {
        int ci0 = chunk << 4;
        // ---- stage B: x halo tile, pair-packed along ci ----
        for (int tsk = tid; tsk < 384; tsk += 256) {
            int srow = tsk >> 7;
            int rem = tsk & 127;
            int pair = rem >> 4, cg = rem & 15;
            int gy = ytile - 1 + srow;
            int sb = (srow * 8 + pair) * 72 + 1 + (cg << 2);
            if ((unsigned)gy < 64u) {
                long e = xbase + (long)(ci0 + (pair << 1)) * NN + (gy << 6) + (cg << 2);
                long o = e + NN;
                uint32_t e0 = *(const uint32_t*)(xh + e);
                uint32_t e1 = *(const uint32_t*)(xh + e + 2);
                uint32_t o0 = *(const uint32_t*)(xh + o);
                uint32_t o1 = *(const uint32_t*)(xh + o + 2);
                sBh[sb + 0] = __byte_perm(e0, o0, 0x5410);
                sBh[sb + 1] = __byte_perm(e0, o0, 0x7632);
                sBh[sb + 2] = __byte_perm(e1, o1, 0x5410);
                sBh[sb + 3] = __byte_perm(e1, o1, 0x7632);
                e0 = *(const uint32_t*)(xl + e);
                e1 = *(const uint32_t*)(xl + e + 2);
                o0 = *(const uint32_t*)(xl + o);
                o1 = *(const uint32_t*)(xl + o + 2);
                sBl[sb + 0] = __byte_perm(e0, o0, 0x5410);
                sBl[sb + 1] = __byte_perm(e0, o0, 0x7632);
                sBl[sb + 2] = __byte_perm(e1, o1, 0x5410);
                sBl[sb + 3] = __byte_perm(e1, o1, 0x7632);
            } else {
#pragma unroll
                for (int z = 0; z < 4; z++) { sBh[sb + z] = 0; sBl[sb + z] = 0; }
            }
        }
        if (tid < 48) {
            int srow = tid / 16, rem = tid % 16;
            int pair = rem >> 1, edge = rem & 1;
            int off = (srow * 8 + pair) * 72 + (edge ? 65 : 0);
            sBh[off] = 0;
            sBl[off] = 0;
        }
        // ---- stage A: all 9 kaps of this chunk (contiguous in packed W) ---
        {
            long wb = (long)chunk * 9 * 2048 + (long)0;
            // global idx = ((chunk*9+kap)*256 + co0 + row)*8 + col
            for (int idx = tid; idx < 9216; idx += 256) {
                int kap = idx >> 10;
                int rem = idx & 1023;
                int row = rem >> 3, col = rem & 7;
                long g = wb + (long)kap * 2048 + ((long)(co0 + row) << 3) + col;
                sAh[kap * 1152 + row * 9 + col] = wph[g];
                sAl[kap * 1152 + row * 9 + col] = wpl[g];
            }
        }
        __syncthreads();

#pragma unroll
        for (int kap = 0; kap < 9; kap++) {
            int dy = kap / 3, dx = kap - dy * 3;
            uint32_t ah[2][4], al[2][4];
#pragma unroll
            for (int mf = 0; mf < 2; mf++) {
                int mr = (wm << 5) + (mf << 4);
                int ab = kap * 1152 + (mr + grp) * 9;
                ah[mf][0] = sAh[ab + tig];
                ah[mf][1] = sAh[ab + 72 + tig];       // +8 rows * 9
                ah[mf][2] = sAh[ab + tig + 4];
                ah[mf][3] = sAh[ab + 72 + tig + 4];
                al[mf][0] = sAl[ab + tig];
                al[mf][1] = sAl[ab + 72 + tig];
                al[mf][2] = sAl[ab + tig + 4];
                al[mf][3] = sAl[ab + 72 + tig + 4];
            }
#pragma unroll
            for (int nf = 0; nf < 4; nf++) {
                int n = (wn << 5) + (nf << 3) + grp;
                int a0 = (dy * 8 + tig) * 72 + n + dx;
                uint32_t bh0 = sBh[a0];
                uint32_t bh1 = sBh[a0 + 288];
                uint32_t bl0 = sBl[a0];
                uint32_t bl1 = sBl[a0 + 288];
#pragma unroll
                for (int mf = 0; mf < 2; mf++) {
                    mma_bf16(acc[mf][nf], ah[mf], bh0, bh1);
                    mma_bf16(acc[mf][nf], ah[mf], bl0, bl1);
                    mma_bf16(acc[mf][nf], al[mf], bh0, bh1);
                }
            }
        }
        __syncthreads();
    }
#pragma unroll
    for (int mf = 0; mf < 2; mf++) {
        int r0 = co0 + (wm << 5) + (mf << 4) + grp;
#pragma unroll
        for (int nf = 0; nf < 4; nf++) {
            int p = (ytile << 6) + (wn << 5) + (nf << 3) + (tig << 1);
            *(float2*)&out[((long)(b * CC + r0) << 12) + p] =
                make_float2(acc[mf][nf][0], acc[mf][nf][1]);
            *(float2*)&out[((long)(b * CC + r0 + 8) << 12) + p] =
                make_float2(acc[mf][nf][2], acc[mf][nf][3]);
        }
    }
}

// ---------------- instance norm + relu -> bf16 split ----------------------
__global__ __launch_bounds__(256) void k_inorm0(const float* __restrict__ t,
                                                __nv_bfloat16* __restrict__ oh,
                                                __nv_bfloat16* __restrict__ ol) {
    long base = (long)blockIdx.x * NN;
    int tid = threadIdx.x;
    float s = 0.f, s2 = 0.f;
    for (int i = tid; i < NN; i += 256) {
        float v = t[base + i];
        s += v;
        s2 = fmaf(v, v, s2);
    }
    __shared__ float sh[16];
    __shared__ float smu, srs;
    s = warpSum(s);
    s2 = warpSum(s2);
    int wi = tid >> 5, l = tid & 31;
    if (l == 0) { sh[wi] = s; sh[8 + wi] = s2; }
    __syncthreads();
    if (tid == 0) {
        float a = 0.f, b2 = 0.f;
#pragma unroll
        for (int i = 0; i < 8; i++) { a += sh[i]; b2 += sh[8 + i]; }
        float mu = a * (1.f / NN);
        float var = b2 * (1.f / NN) - mu * mu;
        smu = mu;
        srs = rsqrtf(var + EPS_IN);
    }
    __syncthreads();
    float mu = smu, rs = srs;
    for (int i = tid; i < NN; i += 256) {
        float v = fmaxf((t[base + i] - mu) * rs, 0.f);
        __nv_bfloat16 h = __float2bfloat16(v);
        oh[base + i] = h;
        ol[base + i] = __float2bfloat16(v - __bfloat162float(h));
    }
}

// ---------------- instance norm + residual + relu -> fp32 -----------------
__global__ __launch_bounds__(256) void k_inorm1(const float* __restrict__ t,
                                                const float* __restrict__ xadd,
                                                float* __restrict__ o) {
    long base = (long)blockIdx.x * NN;
    int tid = threadIdx.x;
    float s = 0.f, s2 = 0.f;
    for (int i = tid; i < NN; i += 256) {
        float v = t[base + i];
        s += v;
        s2 = fmaf(v, v, s2);
    }
    __shared__ float sh[16];
    __shared__ float smu, srs;
    s = warpSum(s);
    s2 = warpSum(s2);
    int wi = tid >> 5, l = tid & 31;
    if (l == 0) { sh[wi] = s; sh[8 + wi] = s2; }
    __syncthreads();
    if (tid == 0) {
        float a = 0.f, b2 = 0.f;
#pragma unroll
        for (int i = 0; i < 8; i++) { a += sh[i]; b2 += sh[8 + i]; }
        float mu = a * (1.f / NN);
        float var = b2 * (1.f / NN) - mu * mu;
        smu = mu;
        srs = rsqrtf(var + EPS_IN);
    }
    __syncthreads();
    float mu = smu, rs = srs;
    for (int i = tid; i < NN; i += 256)
        o[base + i] = fmaxf((t[base + i] - mu) * rs + xadd[base + i], 0.f);
}

// ---------------- per-pixel channel L2 norm reciprocal --------------------
__global__ void k_rn(const float* __restrict__ feat) {
    int gid = blockIdx.x * 256 + threadIdx.x;
    int b = gid >> 12;
    int px = gid & 4095;
    const float* fb = feat + (long)b * CC * NN + px;
    float s = 0.f;
    for (int c = 0; c < CC; c++) {
        float f = fb[c << 12];
        s = fmaf(f, f, s);
    }
    g_rn[gid] = 1.f / (sqrtf(s) + EPS_NORM);
}

// ---------------- gather: packed bf16 Q/K + fp32 Xq/Vc --------------------
// grid (16, 2, BB); y=0: queries -> Qph/Qpl/Xq ; y=1: keys -> Kph/Kpl/Vc
__global__ __launch_bounds__(256) void k_gather(const float* __restrict__ feat,
                                                const float* __restrict__ x) {
    int b = blockIdx.z;
    int side = blockIdx.y;
    int i = (blockIdx.x << 8) + threadIdx.x;
    int n = side ? g_nk[b] : g_nq[b];
    int npad = PAD128(n);
    if (i >= npad) return;
    uint32_t* Ph = side ? g_Kph : g_Qph;
    uint32_t* Pl = side ? g_Kpl : g_Qpl;
    float* B2 = side ? g_Vc : g_Xq;
    long off = (long)b * CC * NN;
    long poff = ((long)b << 7 << 12);
    if (i < n) {
        int px = side ? g_kidx[(b << 12) + i] : g_qidx[(b << 12) + i];
        float rn = g_rn[(b << 12) + px];
        const float* fb = feat + off + px;
        const float* xb = x + off + px;
        for (int c = 0; c < CC; c += 2) {
            float v0 = fb[c << 12] * rn;
            float v1 = fb[(c + 1) << 12] * rn;
            __nv_bfloat16 h0 = __float2bfloat16(v0);
            __nv_bfloat16 h1 = __float2bfloat16(v1);
            long pi = poff + ((long)(c >> 1) << 12) + i;
            Ph[pi] = pack2bf(v0, v1);
            Pl[pi] = pack2bf(v0 - __bfloat162float(h0), v1 - __bfloat162float(h1));
            B2[off + (c << 12) + i] = xb[c << 12];
            B2[off + ((c + 1) << 12) + i] = xb[(c + 1) << 12];
        }
    } else {
        for (int c = 0; c < CC; c += 2) {
            long pi = poff + ((long)(c >> 1) << 12) + i;
            Ph[pi] = 0; Pl[pi] = 0;
            B2[off + (c << 12) + i] = 0.f;
            B2[off + ((c + 1) << 12) + i] = 0.f;
        }
    }
}

// ---------------- pack V fp32 -> bf16 hi/lo pairs along j -----------------
__global__ void k_packV(const float* __restrict__ V) {
    int idx = blockIdx.x * 256 + threadIdx.x;    // < BB*256*2048
    int b = idx >> 19;
    int rem = idx & 524287;
    int c = rem >> 11, jp = rem & 2047;
    float2 v = *(const float2*)(V + (long)(b * CC + c) * NN + 2 * jp);
    __nv_bfloat16 h0 = __float2bfloat16(v.x);
    __nv_bfloat16 h1 = __float2bfloat16(v.y);
    g_Vph[idx] = pack2bf(v.x, v.y);
    g_Vpl[idx] = pack2bf(v.x - __bfloat162float(h0), v.y - __bfloat162float(h1));
}

// ---------------- score GEMM tensor cores: 128q x 128k --------------------
__global__ __launch_bounds__(256) void k_score_tc(float* __restrict__ att) {
    int b = blockIdx.z;
    int q0 = blockIdx.y << 7;
    int k0 = blockIdx.x << 7;
    if (q0 >= PAD128(g_nq[b]) || k0 >= PAD128(g_nk[b])) return;
    __shared__ uint32_t sQh[128 * 9], sQl[128 * 9];
    __shared__ uint32_t sKh[8 * 136], sKl[8 * 136];
    int tid = threadIdx.x;
    int w = tid >> 5, l = tid & 31;
    int wm = w & 3, wn = w >> 2;
    int grp = l >> 2, tig = l & 3;
    int q = tid & 127, half = tid >> 7;
    long pbase = ((long)b << 7 << 12);

    float acc[2][8][4];
#pragma unroll
    for (int i = 0; i < 2; i++)
#pragma unroll
        for (int j = 0; j < 8; j++)
#pragma unroll
            for (int k = 0; k < 4; k++) acc[i][j][k] = 0.f;

    for (int step = 0; step < 16; step++) {
        int c0p = step << 3;
#pragma unroll
        for (int it = 0; it < 4; it++) {
            int cp = (it << 1) + half;
            long g = pbase + ((long)(c0p + cp) << 12);
            sQh[q * 9 + cp] = g_Qph[g + q0 + q];
            sQl[q * 9 + cp] = g_Qpl[g + q0 + q];
            sKh[cp * 136 + q] = g_Kph[g + k0 + q];
            sKl[cp * 136 + q] = g_Kpl[g + k0 + q];
        }
        __syncthreads();
        uint32_t ah[2][4], al[2][4];
#pragma unroll
        for (int mf = 0; mf < 2; mf++) {
            int ab = ((wm << 5) + (mf << 4) + grp) * 9;
            ah[mf][0] = sQh[ab + tig];
            ah[mf][1] = sQh[ab + 72 + tig];
            ah[mf][2] = sQh[ab + tig + 4];
            ah[mf][3] = sQh[ab + 72 + tig + 4];
            al[mf][0] = sQl[ab + tig];
            al[mf][1] = sQl[ab + 72 + tig];
            al[mf][2] = sQl[ab + tig + 4];
            al[mf][3] = sQl[ab + 72 + tig + 4];
        }
#pragma unroll
        for (int nf = 0; nf < 8; nf++) {
            int n = (wn << 6) + (nf << 3) + grp;
            uint32_t bh0 = sKh[tig * 136 + n];
            uint32_t bh1 = sKh[(tig + 4) * 136 + n];
            uint32_t bl0 = sKl[tig * 136 + n];
            uint32_t bl1 = sKl[(tig + 4) * 136 + n];
#pragma unroll
            for (int mf = 0; mf < 2; mf++) {
                mma_bf16(acc[mf][nf], ah[mf], bh0, bh1);
                mma_bf16(acc[mf][nf], ah[mf], bl0, bl1);
                mma_bf16(acc[mf][nf], al[mf], bh0, bh1);
            }
        }
        __syncthreads();
    }
    float* Cb = att + (long)b * NN * NN;
#pragma unroll
    for (int mf = 0; mf < 2; mf++) {
        int r0 = q0 + (wm << 5) + (mf << 4) + grp;
#pragma unroll
        for (int nf = 0; nf < 8; nf++) {
            int cc = k0 + (wn << 6) + (nf << 3) + (tig << 1);
            *(float2*)&Cb[(long)r0 * NN + cc] =
                make_float2(acc[mf][nf][0] * SCALE, acc[mf][nf][1] * SCALE);
            *(float2*)&Cb[(long)(r0 + 8) * NN + cc] =
                make_float2(acc[mf][nf][2] * SCALE, acc[mf][nf][3] * SCALE);
        }
    }
}

// ---------------- softmax over compacted keys ------------------------------
__global__ __launch_bounds__(256) void k_softmax(float* __restrict__ att) {
    int b = blockIdx.y;
    int i = blockIdx.x;
    int nq = g_nq[b];
    if (i >= nq) return;
    int nk = g_nk[b];
    int nkp = PAD128(nk);
    float* row = att + (long)b * NN * NN + (long)i * NN;
    int tid = threadIdx.x;
    float vals[16];
    float mx = -1e30f;
    int nt = (nkp + 255) >> 8;
#pragma unroll
    for (int t = 0; t < 16; t++) {
        if (t >= nt) break;
        int k = tid + (t << 8);
        float s = (k < nk) ? row[k] : -1e30f;
        vals[t] = s;
        mx = fmaxf(mx, s);
    }
    __shared__ float sh[8];
    __shared__ float bval;
    mx = warpMax(mx);
    int wi = tid >> 5, l = tid & 31;
    if (l == 0) sh[wi] = mx;
    __syncthreads();
    if (tid == 0) {
        float m2 = sh[0];
#pragma unroll
        for (int ii = 1; ii < 8; ii++) m2 = fmaxf(m2, sh[ii]);
        bval = m2;
    }
    __syncthreads();
    mx = bval;
    float sum = 0.f;
#pragma unroll
    for (int t = 0; t < 16; t++) {
        if (t >= nt) break;
        float e = __expf(vals[t] - mx);
        vals[t] = e;
        sum += e;
    }
    sum = warpSum(sum);
    __syncthreads();
    if (l == 0) sh[wi] = sum;
    __syncthreads();
    if (tid == 0) {
        float s2 = 0.f;
#pragma unroll
        for (int ii = 0; ii < 8; ii++) s2 += sh[ii];
        bval = 1.f / s2;
    }
    __syncthreads();
    float rinv = bval;
#pragma unroll
    for (int t = 0; t < 16; t++) {
        if (t >= nt) break;
        int k = tid + (t << 8);
        row[k] = (k < nk) ? vals[t] * rinv : 0.f;
    }
}

// ---------------- pack P (att) -> bf16 hi/lo pairs along j ----------------
// grid (4096, BB), block 256
__global__ void k_packP(const float* __restrict__ att) {
    int b = blockIdx.y;
    int i = blockIdx.x;
    if (i >= PAD128(g_nq[b])) return;
    int nkp2 = PAD128(g_nk[b]) >> 1;
    const float* row = att + (long)b * NN * NN + (long)i * NN;
    uint32_t* oh = g_Pph + ((long)b * NN + i) * 2048;
    uint32_t* ol = g_Ppl + ((long)b * NN + i) * 2048;
    for (int jp = threadIdx.x; jp < nkp2; jp += 256) {
        float2 v = *(const float2*)(row + 2 * jp);
        __nv_bfloat16 h0 = __float2bfloat16(v.x);
        __nv_bfloat16 h1 = __float2bfloat16(v.y);
        oh[jp] = pack2bf(v.x, v.y);
        ol[jp] = pack2bf(v.x - __bfloat162float(h0), v.y - __bfloat162float(h1));
    }
}

// ---------------- visatt: column sums of compacted att --------------------
__global__ void k_visatt(const float* __restrict__ att) {
    int b = blockIdx.y;
    int k0 = blockIdx.x << 6;
    int nk = g_nk[b];
    if (k0 >= nk) return;
    int nq = g_nq[b];
    int kk = threadIdx.x & 63;
    int qq = threadIdx.x >> 6;
    const float* base = att + (long)b * NN * NN + k0 + kk;
    float s = 0.f;
    for (int q = qq; q < nq; q += 4) s += base[(long)q << 12];
    __shared__ float sh[256];
    sh[threadIdx.x] = s;
    __syncthreads();
    if (threadIdx.x < 64) {
        int k = k0 + threadIdx.x;
        if (k < nk) {
            float tot = sh[threadIdx.x] + sh[threadIdx.x + 64] +
                        sh[threadIdx.x + 128] + sh[threadIdx.x + 192];
            g_vis[(b << 12) + g_kidx[(b << 12) + k]] = tot;
        }
    }
}

// ---------------- AV GEMM tensor cores: 128c x 128q -----------------------
__global__ __launch_bounds__(256) void k_av_tc(float* __restrict__ out) {
    int b = blockIdx.z;
    int m0 = blockIdx.y << 7;   // c
    int n0 = blockIdx.x << 7;   // q (compacted)
    if (n0 >= PAD128(g_nq[b])) return;
    int nkp = PAD128(g_nk[b]);
    __shared__ uint32_t sVh[128 * 9], sVl[128 * 9];
    __shared__ uint32_t sPh[8 * 136], sPl[8 * 136];
    int tid = threadIdx.x;
    int w = tid >> 5, l = tid & 31;
    int wm = w & 3, wn = w >> 2;
    int grp = l >> 2, tig = l & 3;
    int r8 = tid >> 3, c8 = tid & 7;    // staging: 32 rows x 8 cols per pass

    float acc[2][8][4];
#pragma unroll
    for (int i = 0; i < 2; i++)
#pragma unroll
        for (int j = 0; j < 8; j++)
#pragma unroll
            for (int k = 0; k < 4; k++) acc[i][j][k] = 0.f;

    long vbase = (long)b * 256 * 2048;
    long pbase = (long)b * NN * 2048;

    for (int jc = 0; jc < nkp; jc += 16) {
        int j0p = jc >> 1;
#pragma unroll
        for (int it = 0; it < 4; it++) {
            int rr = r8 + (it << 5);
            sVh[rr * 9 + c8] = g_Vph[vbase + (long)(m0 + rr) * 2048 + j0p + c8];
            sVl[rr * 9 + c8] = g_Vpl[vbase + (long)(m0 + rr) * 2048 + j0p + c8];
            sPh[c8 * 136 + rr] = g_Pph[pbase + (long)(n0 + rr) * 2048 + j0p + c8];
            sPl[c8 * 136 + rr] = g_Ppl[pbase + (long)(n0 + rr) * 2048 + j0p + c8];
        }
        __syncthreads();
        uint32_t ah[2][4], al[2][4];
#pragma unroll
        for (int mf = 0; mf < 2; mf++) {
            int ab = ((wm << 5) + (mf << 4) + grp) * 9;
            ah[mf][0] = sVh[ab + tig];
            ah[mf][1] = sVh[ab + 72 + tig];
            ah[mf][2] = sVh[ab + tig + 4];
            ah[mf][3] = sVh[ab + 72 + tig + 4];
            al[mf][0] = sVl[ab + tig];
            al[mf][1] = sVl[ab + 72 + tig];
            al[mf][2] = sVl[ab + tig + 4];
            al[mf][3] = sVl[ab + 72 + tig + 4];
        }
#pragma unroll
        for (int nf = 0; nf < 8; nf++) {
            int n = (wn << 6) + (nf << 3) + grp;
            uint32_t bh0 = sPh[tig * 136 + n];
            uint32_t bh1 = sPh[(tig + 4) * 136 + n];
            uint32_t bl0 = sPl[tig * 136 + n];
            uint32_t bl1 = sPl[(tig + 4) * 136 + n];
#pragma unroll
            for (int mf = 0; mf < 2; mf++) {
                mma_bf16(acc[mf][nf], ah[mf], bh0, bh1);
                mma_bf16(acc[mf][nf], ah[mf], bl0, bl1);
                mma_bf16(acc[mf][nf], al[mf], bh0, bh1);
            }
        }
        __syncthreads();
    }
    float* ob = out + (long)b * CC * NN;
#pragma unroll
    for (int mf = 0; mf < 2; mf++) {
        int r0 = m0 + (wm << 5) + (mf << 4) + grp;
#pragma unroll
        for (int nf = 0; nf < 8; nf++) {
            int cc = n0 + (wn << 6) + (nf << 3) + (tig << 1);
            *(float2*)&ob[((long)r0 << 12) + cc] =
                make_float2(acc[mf][nf][0], acc[mf][nf][1]);
            *(float2*)&ob[((long)(r0 + 8) << 12) + cc] =
                make_float2(acc[mf][nf][2], acc[mf][nf][3]);
        }
    }
}

// ---------------- fuse 1x1 conv + scatter ----------------------------------
__global__ __launch_bounds__(256) void k_gemm_fuse(const float* __restrict__ wf,
                                                   const float* __restrict__ afore,
                                                   const float* __restrict__ xq,
                                                   float* __restrict__ out) {
    int b = blockIdx.z;
    int m0 = blockIdx.y << 7;
    int n0 = blockIdx.x << 7;
    int nq = g_nq[b];
    if (n0 >= PAD128(nq)) return;
    __shared__ float As[16][128];
    __shared__ float Bs[16][128];
    int tid = threadIdx.x;
    int mb = (tid >> 4) << 3;
    int nb = (tid & 15) << 3;
    float acc[8][8];
#pragma unroll
    for (int i = 0; i < 8; i++)
#pragma unroll
        for (int j = 0; j < 8; j++) acc[i][j] = 0.f;

    for (int kc = 0; kc < 2 * CC; kc += 16) {
#pragma unroll
        for (int t = 0; t < 2; t++) {
            int fid = tid + (t << 8);
            int rr = fid >> 2;
            int kb = (fid & 3) << 2;
            float4 av = *(const float4*)(wf + (long)(m0 + rr) * 512 + kc + kb);
            As[kb + 0][rr] = av.x; As[kb + 1][rr] = av.y;
            As[kb + 2][rr] = av.z; As[kb + 3][rr] = av.w;
            int row = fid >> 5;
            int col = (fid & 31) << 2;
            int kki = kc + row;
            const float* src = (kki < CC) ? (afore + (long)(b * CC + kki) * NN)
                                          : (xq + (long)(b * CC + kki - CC) * NN);
            *(float4*)&Bs[row][col] = *(const float4*)(src + n0 + col);
        }
        __syncthreads();
#pragma unroll
        for (int kk = 0; kk < 16; kk++) {
            float a[8], bb[8];
            *(float4*)&a[0] = *(float4*)&As[kk][mb];
            *(float4*)&a[4] = *(float4*)&As[kk][mb + 4];
            *(float4*)&bb[0] = *(float4*)&Bs[kk][nb];
            *(float4*)&bb[4] = *(float4*)&Bs[kk][nb + 4];
#pragma unroll
            for (int i = 0; i < 8; i++)
#pragma unroll
                for (int j = 0; j < 8; j++) acc[i][j] = fmaf(a[i], bb[j], acc[i][j]);
        }
        __syncthreads();
    }
    const int* qidx = g_qidx + (b << 12);
#pragma unroll
    for (int j = 0; j < 8; j++) {
        int i = n0 + nb + j;
        if (i < nq) {
            int px = qidx[i];
#pragma unroll
            for (int ii = 0; ii < 8; ii++) {
                int co = m0 + mb + ii;
                out[((b * CC + co) << 12) + px] = acc[ii][j];
            }
        }
    }
}

// ---------------- global max of visatt ----------------------------------
__global__ void k_vismax() {
    float mx = -1e30f;
    for (int i = threadIdx.x; i < BB * NN; i += 256) mx = fmaxf(mx, g_vis[i]);
    mx = warpMax(mx);
    __shared__ float sh[8];
    if ((threadIdx.x & 31) == 0) sh[threadIdx.x >> 5] = mx;
    __syncthreads();
    if (threadIdx.x == 0) {
        float m2 = sh[0];
#pragma unroll
        for (int i = 1; i < 8; i++) m2 = fmaxf(m2, sh[i]);
        g_maxv[0] = m2;
    }
}

// ---------------- attmask --------------------------------------------------
__global__ void k_attmask(float* __restrict__ o) {
    int i = blockIdx.x * 256 + threadIdx.x;
    int b = i >> 18;
    int r = i & 262143;
    int Y = r >> 9, X = r & 511;
    o[i] = g_vis[(b << 12) + ((Y >> 3) << 6) + (X >> 3)] / g_maxv[0];
}

// ---------------- launch -------------------------------------------------
extern "C" void kernel_launch(void* const* d_in, const int* in_sizes, int n_in,
                              void* d_out, int out_size) {
    const float* x = nullptr;
    const float* mask = nullptr;
    const float* w1 = nullptr;
    const float* w2 = nullptr;
    const float* wf = nullptr;
    int seen589 = 0;
    for (int i = 0; i < n_in; i++) {
        switch (in_sizes[i]) {
            case 2097152: x = (const float*)d_in[i]; break;
            case 524288:  mask = (const float*)d_in[i]; break;
            case 589824:
                if (seen589++ == 0) w1 = (const float*)d_in[i];
                else w2 = (const float*)d_in[i];
                break;
            case 131072:  wf = (const float*)d_in[i]; break;
            default: break;
        }
    }

    float *bufA, *bufB, *Vc, *Xq, *att;
    __nv_bfloat16 *xh, *xl, *f1h, *f1l;
    uint32_t *w1h, *w1l, *w2h, *w2l;
    cudaGetSymbolAddress((void**)&bufA, g_bufA);
    cudaGetSymbolAddress((void**)&bufB, g_bufB);
    cudaGetSymbolAddress((void**)&Vc, g_Vc);
    cudaGetSymbolAddress((void**)&Xq, g_Xq);
    cudaGetSymbolAddress((void**)&att, g_att);
    cudaGetSymbolAddress((void**)&xh, g_xh);
    cudaGetSymbolAddress((void**)&xl, g_xl);
    cudaGetSymbolAddress((void**)&f1h, g_f1h);
    cudaGetSymbolAddress((void**)&f1l, g_f1l);
    cudaGetSymbolAddress((void**)&w1h, g_w1h);
    cudaGetSymbolAddress((void**)&w1l, g_w1l);
    cudaGetSymbolAddress((void**)&w2h, g_w2h);
    cudaGetSymbolAddress((void**)&w2l, g_w2l);

    static int smem_set = 0;
    const int CONV_SMEM = (10368 * 2 + 1728 * 2) * 4;   // 96768 B
    if (!smem_set) {
        cudaFuncSetAttribute(k_conv_tc, cudaFuncAttributeMaxDynamicSharedMemorySize,
                             CONV_SMEM);
        smem_set = 1;
    }

    float* out = (float*)d_out;
    float* attm = out + (long)BB * CC * NN;

    cudaMemcpyAsync(out, x, (size_t)BB * CC * NN * sizeof(float),
                    cudaMemcpyDeviceToDevice);

    k_mask<<<32, 256>>>(mask);
    k_compact<<<BB, 256>>>();
    k_packW<<<1152, 256>>>(w1, w1h, w1l);
    k_packW<<<1152, 256>>>(w2, w2h, w2l);
    k_packX<<<8192, 256>>>(x, xh, xl);
    k_conv_tc<<<dim3(64, 2, BB), 256, CONV_SMEM>>>(xh, xl, w1h, w1l, bufA);
    k_inorm0<<<BB * CC, 256>>>(bufA, f1h, f1l);
    k_conv_tc<<<dim3(64, 2, BB), 256, CONV_SMEM>>>(f1h, f1l, w2h, w2l, bufA);
    k_inorm1<<<BB * CC, 256>>>(bufA, x, bufB);            // bufB = feat
    k_rn<<<32, 256>>>(bufB);
    k_gather<<<dim3(16, 2, BB), 256>>>(bufB, x);
    k_packV<<<4096, 256>>>(Vc);
    k_score_tc<<<dim3(32, 32, BB), 256>>>(att);
    k_softmax<<<dim3(4096, BB), 256>>>(att);
    k_packP<<<dim3(4096, BB), 256>>>(att);
    k_visatt<<<dim3(64, BB), 256>>>(att);
    k_av_tc<<<dim3(32, 2, BB), 256>>>(bufA);              // bufA = AFq
    k_vismax<<<1, 256>>>();
    k_gemm_fuse<<<dim3(32, 2, BB), 256>>>(wf, bufA, Xq, out);
    k_attmask<<<2048, 256>>>(attm);
}